// round 2
// baseline (speedup 1.0000x reference)
#include <cuda_runtime.h>
#include <cuda_bf16.h>
#include <stdint.h>

// Problem constants
#define BB 8
#define NN 2048
#define HH 512
#define KNB 8            // neighbors kept
#define NSEL 9           // top-(K+1) selected, rank0 dropped
#define NLAYERS 3
#define LN_EPS 1e-5f

#define ADJ_WORDS 64     // 2048 bits / 32
#define MTOT (BB*NN)     // 16384 rows

// ---------------- device scratch (no allocations allowed) ----------------
__device__ uint32_t g_adj[BB * NN * ADJ_WORDS];          // 4 MB adjacency bitmask
__device__ float4   g_x4[BB * NN * (HH/4)];              // 32 MB current x
__device__ float4   g_agg4[BB * NN * (HH/4)];            // 32 MB aggregated

// ---------------- kernel 0: zero adjacency ----------------
__global__ void zero_adj_kernel() {
    int i = blockIdx.x * blockDim.x + threadIdx.x;
    if (i < BB * NN * ADJ_WORDS) g_adj[i] = 0u;
}

// ---------------- kernel 1: top-k + adjacency build ----------------
// One block per (b, n) row. Exact replication of jax.lax.top_k(-d2, 9):
// ascending d2, ties broken by lower index; rank 0 dropped.
__global__ void __launch_bounds__(256) topk_adj_kernel(const float2* __restrict__ coords) {
    __shared__ float2 sc[NN];
    __shared__ unsigned long long key[NN];
    __shared__ unsigned long long warpmin[8];

    const int b = blockIdx.y;
    const int n = blockIdx.x;
    const int tid = threadIdx.x;
    const int lane = tid & 31;
    const int wid  = tid >> 5;

    const float2* cb = coords + (size_t)b * NN;
    for (int i = tid; i < NN; i += 256) sc[i] = cb[i];
    __syncthreads();

    const float xn = sc[n].x, yn = sc[n].y;
    // sq = x*x + y*y, plain mul+add (XLA reduce over 2 elems)
    const float sqn = __fadd_rn(__fmul_rn(xn, xn), __fmul_rn(yn, yn));

    for (int m = tid; m < NN; m += 256) {
        const float xm = sc[m].x, ym = sc[m].y;
        const float sqm = __fadd_rn(__fmul_rn(xm, xm), __fmul_rn(ym, ym));
        // einsum k=2 contraction: FMA-accumulated, k ascending (x first):
        //   acc = rn(x_n*x_m); acc = fma(y_n, y_m, acc)
        const float dot = __fmaf_rn(yn, ym, __fmul_rn(xn, xm));
        // d2 = (sqn + sqm) - 2*dot   (2*dot exact; fsub == fma(-2,dot,s) here)
        const float d2  = __fsub_rn(__fadd_rn(sqn, sqm), __fmul_rn(2.0f, dot));
        // order-preserving encode: (d2 ascending, index ascending)
        uint32_t fb = __float_as_uint(d2);
        fb = (fb & 0x80000000u) ? ~fb : (fb | 0x80000000u);
        key[m] = ((unsigned long long)fb << 32) | (uint32_t)m;
    }
    __syncthreads();

    for (int r = 0; r < NSEL; r++) {
        unsigned long long best = ~0ull;
        #pragma unroll
        for (int m = tid; m < NN; m += 256) {
            unsigned long long k = key[m];
            best = (k < best) ? k : best;
        }
        #pragma unroll
        for (int off = 16; off > 0; off >>= 1) {
            unsigned long long o = __shfl_down_sync(0xffffffffu, best, off);
            best = (o < best) ? o : best;
        }
        if (lane == 0) warpmin[wid] = best;
        __syncthreads();
        if (tid == 0) {
            unsigned long long g = warpmin[0];
            #pragma unroll
            for (int w = 1; w < 8; w++) {
                unsigned long long o = warpmin[w];
                g = (o < g) ? o : g;
            }
            const int m = (int)(g & 0xffffffffu);
            key[m] = ~0ull;                    // remove winner for next round
            if (r > 0) {                       // rank 0 dropped (== idx[:, :, 1:])
                atomicOr(&g_adj[((size_t)b * NN + n) * ADJ_WORDS + (m >> 5)], 1u << (m & 31));
                atomicOr(&g_adj[((size_t)b * NN + m) * ADJ_WORDS + (n >> 5)], 1u << (n & 31));
            }
        }
        __syncthreads();
    }
}

// ---------------- kernel 2: sparse aggregation  agg[b,n,:] = sum_{m in adj(n)} x[b,m,:]
// One block (128 threads) per node; each thread owns a float4 (4 features).
__global__ void __launch_bounds__(128) agg_kernel(const float4* __restrict__ xin) {
    __shared__ uint32_t rowbits[ADJ_WORDS];
    const int b = blockIdx.y;
    const int n = blockIdx.x;
    const int t = threadIdx.x;

    const uint32_t* row = &g_adj[((size_t)b * NN + n) * ADJ_WORDS];
    if (t < ADJ_WORDS) rowbits[t] = row[t];
    __syncthreads();

    const float4* xb = xin + (size_t)b * NN * (HH/4);
    float4 acc = make_float4(0.f, 0.f, 0.f, 0.f);

    #pragma unroll 4
    for (int w = 0; w < ADJ_WORDS; w++) {
        uint32_t bits = rowbits[w];
        while (bits) {
            const int bit = __ffs(bits) - 1;
            bits &= bits - 1;
            const int m = (w << 5) + bit;
            const float4 v = __ldg(&xb[(size_t)m * (HH/4) + t]);
            acc.x += v.x; acc.y += v.y; acc.z += v.z; acc.w += v.w;
        }
    }
    g_agg4[((size_t)b * NN + n) * (HH/4) + t] = acc;
}

// ---------------- kernel 3: GEMM (16384x512 @ 512x512) + bias + LN + ReLU + residual
// Block: 256 threads computes 32 rows x 512 cols. Thread (ty=tid/32, tx=tid%32)
// owns rows [4*ty..4*ty+3], cols {4*tx + 128*j + q}.  Warp ty owns 4 full rows
// -> LN reduction is a pure warp shuffle.
__global__ void __launch_bounds__(256, 2) gemm_ln_kernel(
    const float* __restrict__ A,        // [16384, 512] aggregated
    const float* __restrict__ Wl,       // [512, 512] row-major (K x N)
    const float* __restrict__ bl,       // [512]
    const float* __restrict__ gl,       // [512]
    const float* __restrict__ btl,      // [512]
    const float* __restrict__ resid,    // [16384, 512] or nullptr
    float* __restrict__ out)            // [16384, 512]
{
    __shared__ float Bs[8][HH];         // 16 KB
    __shared__ float As[8][32];         // 1 KB

    const int tid = threadIdx.x;
    const int tx = tid & 31;
    const int ty = tid >> 5;
    const int row0 = blockIdx.x * 32;

    float4 acc[4][4];
    #pragma unroll
    for (int i = 0; i < 4; i++)
        #pragma unroll
        for (int j = 0; j < 4; j++)
            acc[i][j] = make_float4(0.f, 0.f, 0.f, 0.f);

    const float4* Wv = (const float4*)Wl;
    const int ar = tid >> 3;                 // 0..31 (row within tile)
    const int ak = tid & 7;                  // 0..7  (k within chunk)
    const float* Arow = A + (size_t)(row0 + ar) * HH + ak;

    for (int k0 = 0; k0 < HH; k0 += 8) {
        // load W chunk: 8 x 512 floats = 1024 float4, 4 per thread, coalesced
        #pragma unroll
        for (int q = 0; q < 4; q++) {
            const int idx = tid + q * 256;   // 0..1023
            const int kk  = idx >> 7;
            const int c4  = idx & 127;
            ((float4*)Bs[kk])[c4] = Wv[(size_t)(k0 + kk) * (HH/4) + c4];
        }
        // load A chunk: 32 rows x 8 k, one float per thread (32B/row coalesced)
        As[ak][ar] = Arow[k0];
        __syncthreads();

        #pragma unroll
        for (int kk = 0; kk < 8; kk++) {
            const float4 a = *(const float4*)&As[kk][ty << 2];   // warp broadcast
            #pragma unroll
            for (int j = 0; j < 4; j++) {
                const float4 bv = *(const float4*)&Bs[kk][(tx << 2) + (j << 7)];
                acc[0][j].x += a.x * bv.x; acc[0][j].y += a.x * bv.y;
                acc[0][j].z += a.x * bv.z; acc[0][j].w += a.x * bv.w;
                acc[1][j].x += a.y * bv.x; acc[1][j].y += a.y * bv.y;
                acc[1][j].z += a.y * bv.z; acc[1][j].w += a.y * bv.w;
                acc[2][j].x += a.z * bv.x; acc[2][j].y += a.z * bv.y;
                acc[2][j].z += a.z * bv.z; acc[2][j].w += a.z * bv.w;
                acc[3][j].x += a.w * bv.x; acc[3][j].y += a.w * bv.y;
                acc[3][j].z += a.w * bv.z; acc[3][j].w += a.w * bv.w;
            }
        }
        __syncthreads();
    }

    // ---- epilogue: + bias, LayerNorm (two-pass), *gamma+beta, relu, +resid ----
    #pragma unroll
    for (int j = 0; j < 4; j++) {
        const int c = (tx << 2) + (j << 7);
        const float4 b4 = *(const float4*)&bl[c];
        #pragma unroll
        for (int i = 0; i < 4; i++) {
            acc[i][j].x += b4.x; acc[i][j].y += b4.y;
            acc[i][j].z += b4.z; acc[i][j].w += b4.w;
        }
    }

    #pragma unroll
    for (int i = 0; i < 4; i++) {
        const int row = row0 + (ty << 2) + i;

        float s = 0.f;
        #pragma unroll
        for (int j = 0; j < 4; j++)
            s += acc[i][j].x + acc[i][j].y + acc[i][j].z + acc[i][j].w;
        #pragma unroll
        for (int off = 16; off > 0; off >>= 1)
            s += __shfl_xor_sync(0xffffffffu, s, off);
        const float mu = s * (1.0f / HH);

        float vs = 0.f;
        #pragma unroll
        for (int j = 0; j < 4; j++) {
            float dx = acc[i][j].x - mu, dy = acc[i][j].y - mu;
            float dz = acc[i][j].z - mu, dw = acc[i][j].w - mu;
            vs += dx * dx + dy * dy + dz * dz + dw * dw;
        }
        #pragma unroll
        for (int off = 16; off > 0; off >>= 1)
            vs += __shfl_xor_sync(0xffffffffu, vs, off);
        const float rs = rsqrtf(vs * (1.0f / HH) + LN_EPS);

        #pragma unroll
        for (int j = 0; j < 4; j++) {
            const int c = (tx << 2) + (j << 7);
            const float4 g4  = *(const float4*)&gl[c];
            const float4 bt4 = *(const float4*)&btl[c];
            float4 o;
            o.x = fmaxf((acc[i][j].x - mu) * rs * g4.x + bt4.x, 0.f);
            o.y = fmaxf((acc[i][j].y - mu) * rs * g4.y + bt4.y, 0.f);
            o.z = fmaxf((acc[i][j].z - mu) * rs * g4.z + bt4.z, 0.f);
            o.w = fmaxf((acc[i][j].w - mu) * rs * g4.w + bt4.w, 0.f);
            if (resid != nullptr) {
                const float4 r4 = *(const float4*)&resid[(size_t)row * HH + c];
                o.x += r4.x; o.y += r4.y; o.z += r4.z; o.w += r4.w;
            }
            *(float4*)&out[(size_t)row * HH + c] = o;
        }
    }
}

// ---------------- launcher ----------------
extern "C" void kernel_launch(void* const* d_in, const int* in_sizes, int n_in,
                              void* d_out, int out_size) {
    (void)in_sizes; (void)n_in; (void)out_size;
    const float*  node_features = (const float*)d_in[0];   // [8,2048,512]
    const float2* coords        = (const float2*)d_in[1];  // [8,2048,2]
    const float*  W             = (const float*)d_in[2];   // [3,512,512]
    const float*  bvec          = (const float*)d_in[3];   // [3,512]
    const float*  gamma         = (const float*)d_in[4];   // [3,512]
    const float*  beta          = (const float*)d_in[5];   // [3,512]
    float*        outp          = (float*)d_out;           // [8,2048,512]

    float4* gx;  cudaGetSymbolAddress((void**)&gx,  g_x4);
    float4* gag; cudaGetSymbolAddress((void**)&gag, g_agg4);

    // adjacency
    zero_adj_kernel<<<(BB * NN * ADJ_WORDS + 255) / 256, 256>>>();
    topk_adj_kernel<<<dim3(NN, BB), 256>>>(coords);

    for (int l = 0; l < NLAYERS; l++) {
        const float4* xin = (l == 0) ? (const float4*)node_features : (const float4*)gx;
        agg_kernel<<<dim3(NN, BB), 128>>>(xin);

        const float* resid = (l == 0) ? nullptr : (const float*)gx;
        float* out = (l == NLAYERS - 1) ? outp : (float*)gx;
        gemm_ln_kernel<<<MTOT / 32, 256>>>(
            (const float*)gag,
            W + (size_t)l * HH * HH,
            bvec + (size_t)l * HH,
            gamma + (size_t)l * HH,
            beta + (size_t)l * HH,
            resid, out);
    }
}

// round 6
// speedup vs baseline: 1.6501x; 1.6501x over previous
#include <cuda_runtime.h>
#include <cuda_bf16.h>
#include <stdint.h>

// Problem constants
#define BB 8
#define NN 2048
#define HH 512
#define NSEL 9
#define NLAYERS 3
#define LN_EPS 1e-5f

#define ADJ_WORDS 64
#define MTOT (BB*NN)        // 16384 rows

// ---------------- device scratch ----------------
__device__ uint32_t      g_adj[BB * NN * ADJ_WORDS];     // 4 MB
__device__ float4        g_x4[BB * NN * (HH/4)];         // 32 MB current x (fp32)
__device__ __nv_bfloat16 g_Ahi[MTOT * HH];               // 16 MB agg hi plane
__device__ __nv_bfloat16 g_Alo[MTOT * HH];               // 16 MB agg lo plane
__device__ __nv_bfloat16 g_Wthi[NLAYERS * HH * HH];      // W^T hi  [l][n][k]
__device__ __nv_bfloat16 g_Wtlo[NLAYERS * HH * HH];      // W^T lo

// ---------------- helpers (sm_80+ only; NO tcgen05 anywhere) ----------------
__device__ __forceinline__ uint32_t smem_u32(const void* p) {
    uint32_t a;
    asm("{ .reg .u64 t; cvta.to.shared.u64 t, %1; cvt.u32.u64 %0, t; }" : "=r"(a) : "l"(p));
    return a;
}
__device__ __forceinline__ void ldm_x4(uint32_t* r, uint32_t addr) {
    asm volatile("ldmatrix.sync.aligned.m8n8.x4.shared.b16 {%0,%1,%2,%3}, [%4];"
                 : "=r"(r[0]), "=r"(r[1]), "=r"(r[2]), "=r"(r[3]) : "r"(addr));
}
__device__ __forceinline__ void mma_bf16(float* c, const uint32_t* a, const uint32_t* b) {
    asm volatile("mma.sync.aligned.m16n8k16.row.col.f32.bf16.bf16.f32 "
                 "{%0,%1,%2,%3}, {%4,%5,%6,%7}, {%8,%9}, {%0,%1,%2,%3};"
                 : "+f"(c[0]), "+f"(c[1]), "+f"(c[2]), "+f"(c[3])
                 : "r"(a[0]), "r"(a[1]), "r"(a[2]), "r"(a[3]), "r"(b[0]), "r"(b[1]));
}

// ---------------- kernel 0: zero adjacency ----------------
__global__ void zero_adj_kernel() {
    int i = blockIdx.x * blockDim.x + threadIdx.x;
    if (i < BB * NN * ADJ_WORDS) g_adj[i] = 0u;
}

// ---------------- kernel 1: top-k + adjacency build (passing since R2) ----------------
__global__ void __launch_bounds__(256) topk_adj_kernel(const float2* __restrict__ coords) {
    __shared__ float2 sc[NN];
    __shared__ unsigned long long key[NN];
    __shared__ unsigned long long warpmin[8];

    const int b = blockIdx.y;
    const int n = blockIdx.x;
    const int tid = threadIdx.x;
    const int lane = tid & 31;
    const int wid  = tid >> 5;

    const float2* cb = coords + (size_t)b * NN;
    for (int i = tid; i < NN; i += 256) sc[i] = cb[i];
    __syncthreads();

    const float xn = sc[n].x, yn = sc[n].y;
    const float sqn = __fadd_rn(__fmul_rn(xn, xn), __fmul_rn(yn, yn));

    for (int m = tid; m < NN; m += 256) {
        const float xm = sc[m].x, ym = sc[m].y;
        const float sqm = __fadd_rn(__fmul_rn(xm, xm), __fmul_rn(ym, ym));
        const float dot = __fmaf_rn(yn, ym, __fmul_rn(xn, xm));
        const float d2  = __fsub_rn(__fadd_rn(sqn, sqm), __fmul_rn(2.0f, dot));
        uint32_t fb = __float_as_uint(d2);
        fb = (fb & 0x80000000u) ? ~fb : (fb | 0x80000000u);
        key[m] = ((unsigned long long)fb << 32) | (uint32_t)m;
    }
    __syncthreads();

    for (int r = 0; r < NSEL; r++) {
        unsigned long long best = ~0ull;
        for (int m = tid; m < NN; m += 256) {
            unsigned long long k = key[m];
            best = (k < best) ? k : best;
        }
        #pragma unroll
        for (int off = 16; off > 0; off >>= 1) {
            unsigned long long o = __shfl_down_sync(0xffffffffu, best, off);
            best = (o < best) ? o : best;
        }
        if (lane == 0) warpmin[wid] = best;
        __syncthreads();
        if (tid == 0) {
            unsigned long long g = warpmin[0];
            #pragma unroll
            for (int w = 1; w < 8; w++) {
                unsigned long long o = warpmin[w];
                g = (o < g) ? o : g;
            }
            const int m = (int)(g & 0xffffffffu);
            key[m] = ~0ull;
            if (r > 0) {
                atomicOr(&g_adj[((size_t)b * NN + n) * ADJ_WORDS + (m >> 5)], 1u << (m & 31));
                atomicOr(&g_adj[((size_t)b * NN + m) * ADJ_WORDS + (n >> 5)], 1u << (n & 31));
            }
        }
        __syncthreads();
    }
}

// ---------------- kernel 2: transpose + bf16-split W  ->  Wt[l][n][k] ----------------
__global__ void convw_kernel(const float* __restrict__ W) {
    __shared__ float tile[32][33];
    const int l  = blockIdx.z;
    const int k0 = blockIdx.y * 32;
    const int n0 = blockIdx.x * 32;
    const int tx = threadIdx.x;       // 0..31
    const int ty = threadIdx.y;       // 0..7

    #pragma unroll
    for (int i = 0; i < 4; i++)
        tile[ty + i * 8][tx] = W[(size_t)l * HH * HH + (size_t)(k0 + ty + i * 8) * HH + n0 + tx];
    __syncthreads();

    #pragma unroll
    for (int i = 0; i < 4; i++) {
        const int n = n0 + ty + i * 8;
        const int k = k0 + tx;
        const float v = tile[tx][ty + i * 8];
        const __nv_bfloat16 hi = __float2bfloat16_rn(v);
        const __nv_bfloat16 lo = __float2bfloat16_rn(v - __bfloat162float(hi));
        g_Wthi[(size_t)l * HH * HH + (size_t)n * HH + k] = hi;
        g_Wtlo[(size_t)l * HH * HH + (size_t)n * HH + k] = lo;
    }
}

// ---------------- kernel 3: sparse aggregation -> bf16 hi/lo planes ----------------
__global__ void __launch_bounds__(128) agg_kernel(const float4* __restrict__ xin) {
    __shared__ uint32_t rowbits[ADJ_WORDS];
    const int b = blockIdx.y;
    const int n = blockIdx.x;
    const int t = threadIdx.x;

    const uint32_t* row = &g_adj[((size_t)b * NN + n) * ADJ_WORDS];
    if (t < ADJ_WORDS) rowbits[t] = row[t];
    __syncthreads();

    const float4* xb = xin + (size_t)b * NN * (HH/4);
    float4 acc = make_float4(0.f, 0.f, 0.f, 0.f);

    #pragma unroll 4
    for (int w = 0; w < ADJ_WORDS; w++) {
        uint32_t bits = rowbits[w];
        while (bits) {
            const int bit = __ffs(bits) - 1;
            bits &= bits - 1;
            const int m = (w << 5) + bit;
            const float4 v = __ldg(&xb[(size_t)m * (HH/4) + t]);
            acc.x += v.x; acc.y += v.y; acc.z += v.z; acc.w += v.w;
        }
    }

    const __nv_bfloat16 hx = __float2bfloat16_rn(acc.x);
    const __nv_bfloat16 hy = __float2bfloat16_rn(acc.y);
    const __nv_bfloat16 hz = __float2bfloat16_rn(acc.z);
    const __nv_bfloat16 hw = __float2bfloat16_rn(acc.w);
    __nv_bfloat162 h01; h01.x = hx; h01.y = hy;
    __nv_bfloat162 h23; h23.x = hz; h23.y = hw;
    __nv_bfloat162 l01, l23;
    l01.x = __float2bfloat16_rn(acc.x - __bfloat162float(hx));
    l01.y = __float2bfloat16_rn(acc.y - __bfloat162float(hy));
    l23.x = __float2bfloat16_rn(acc.z - __bfloat162float(hz));
    l23.y = __float2bfloat16_rn(acc.w - __bfloat162float(hw));

    const size_t base = ((size_t)b * NN + n) * (HH/2) + 2 * t;  // bfloat162 units
    ((__nv_bfloat162*)g_Ahi)[base]     = h01;
    ((__nv_bfloat162*)g_Ahi)[base + 1] = h23;
    ((__nv_bfloat162*)g_Alo)[base]     = l01;
    ((__nv_bfloat162*)g_Alo)[base + 1] = l23;
}

// ---------------- kernel 4: mma.sync bf16-split GEMM + bias + LN + ReLU + residual ----
// CTA: 64 rows x 512 cols, 512 threads = 16 warps (2 M x 8 N), warp tile 32x64.
// Smem rows padded to 40 bf16 (80 B) -> ldmatrix conflict-free.
#define SA_HI 0                        // 64 x 40 bf16 = 5120 B
#define SA_LO 5120
#define SW_HI 10240                    // 512 x 40 bf16 = 40960 B
#define SW_LO 51200
#define SG_BIAS 92160                  // 512 f
#define SG_GAMMA 94208
#define SG_BETA 96256
#define SG_PSUM 98304                  // 64 x 8 f
#define SG_PSQ  100352
#define SG_MU   102400                 // 64 f
#define SG_RS   102656
#define SM_TOTAL2 102912

__global__ void __launch_bounds__(512, 1) gemm_mma_kernel(
    const __nv_bfloat16* __restrict__ Ahi, const __nv_bfloat16* __restrict__ Alo,
    const __nv_bfloat16* __restrict__ Whi, const __nv_bfloat16* __restrict__ Wlo,
    const float* __restrict__ bl, const float* __restrict__ gl, const float* __restrict__ btl,
    const float* __restrict__ resid, float* __restrict__ out)
{
    extern __shared__ char smem[];
    const uint32_t sbase = smem_u32(smem);
    const int tid  = threadIdx.x;
    const int lane = tid & 31;
    const int wid  = tid >> 5;
    const int mwarp = wid >> 3;        // 0..1
    const int nwarp = wid & 7;         // 0..7
    const int row0 = blockIdx.x * 64;

    if (tid < 512) {
        ((float*)(smem + SG_BIAS))[tid]  = __ldg(&bl[tid]);
        ((float*)(smem + SG_GAMMA))[tid] = __ldg(&gl[tid]);
        ((float*)(smem + SG_BETA))[tid]  = __ldg(&btl[tid]);
    }

    float c[16][4];
    #pragma unroll
    for (int f = 0; f < 16; f++)
        #pragma unroll
        for (int q = 0; q < 4; q++) c[f][q] = 0.f;

    for (int chk = 0; chk < 16; chk++) {
        const int kc0 = chk * 32;
        // A tiles: 64 rows x 32 bf16 per plane, one uint2 (4 bf16) per thread
        {
            const int r = tid >> 3, kq = (tid & 7) * 4;
            const uint2 h = __ldg((const uint2*)&Ahi[(size_t)(row0 + r) * HH + kc0 + kq]);
            const uint2 l = __ldg((const uint2*)&Alo[(size_t)(row0 + r) * HH + kc0 + kq]);
            *(uint2*)(smem + SA_HI + r * 80 + kq * 2) = h;
            *(uint2*)(smem + SA_LO + r * 80 + kq * 2) = l;
        }
        // W tiles: 512 rows x 32 bf16 per plane, 4 uint4 per thread
        #pragma unroll
        for (int i = 0; i < 4; i++) {
            const int v = tid + i * 512;
            const int r = v >> 2, kq = (v & 3) * 8;
            const uint4 h = __ldg((const uint4*)&Whi[(size_t)r * HH + kc0 + kq]);
            const uint4 l = __ldg((const uint4*)&Wlo[(size_t)r * HH + kc0 + kq]);
            *(uint4*)(smem + SW_HI + r * 80 + kq * 2) = h;
            *(uint4*)(smem + SW_LO + r * 80 + kq * 2) = l;
        }
        __syncthreads();

        #pragma unroll
        for (int ks = 0; ks < 2; ks++) {
            // A fragment address (m16k16 via 4x m8n8): mat = lane>>3
            const int amat = lane >> 3;
            const int arow = (amat & 1) * 8 + (lane & 7);
            const int akb  = (ks * 16 + (amat >> 1) * 8) * 2;
            uint32_t ah[2][4], al[2][4], bb[8][2];
            #pragma unroll
            for (int mi = 0; mi < 2; mi++) {
                const uint32_t ra = mwarp * 32 + mi * 16 + arow;
                ldm_x4(ah[mi], sbase + SA_HI + ra * 80 + akb);
                ldm_x4(al[mi], sbase + SA_LO + ra * 80 + akb);
            }
            // B fragments (k16n8 pairs via x4): mats {n0k0,n0k8,n8k0,n8k8}
            const int bmat = lane >> 3;
            const int bn   = (bmat >> 1) * 8 + (lane & 7);
            const int bkb  = (ks * 16 + (bmat & 1) * 8) * 2;
            #pragma unroll
            for (int g = 0; g < 4; g++) {
                uint32_t r[4];
                ldm_x4(r, sbase + SW_HI + (uint32_t)(nwarp * 64 + g * 16 + bn) * 80 + bkb);
                bb[g*2][0] = r[0]; bb[g*2][1] = r[1];
                bb[g*2+1][0] = r[2]; bb[g*2+1][1] = r[3];
            }
            // pass 1: Ahi * Whi ; pass 2: Alo * Whi
            #pragma unroll
            for (int mi = 0; mi < 2; mi++)
                #pragma unroll
                for (int ni = 0; ni < 8; ni++) mma_bf16(c[mi*8+ni], ah[mi], bb[ni]);
            #pragma unroll
            for (int mi = 0; mi < 2; mi++)
                #pragma unroll
                for (int ni = 0; ni < 8; ni++) mma_bf16(c[mi*8+ni], al[mi], bb[ni]);
            // pass 3: Ahi * Wlo (reload B from lo plane)
            #pragma unroll
            for (int g = 0; g < 4; g++) {
                uint32_t r[4];
                ldm_x4(r, sbase + SW_LO + (uint32_t)(nwarp * 64 + g * 16 + bn) * 80 + bkb);
                bb[g*2][0] = r[0]; bb[g*2][1] = r[1];
                bb[g*2+1][0] = r[2]; bb[g*2+1][1] = r[3];
            }
            #pragma unroll
            for (int mi = 0; mi < 2; mi++)
                #pragma unroll
                for (int ni = 0; ni < 8; ni++) mma_bf16(c[mi*8+ni], ah[mi], bb[ni]);
        }
        __syncthreads();
    }

    // ---------------- epilogue: bias + LN + ReLU + residual ----------------
    float* bias_s  = (float*)(smem + SG_BIAS);
    float* gamma_s = (float*)(smem + SG_GAMMA);
    float* beta_s  = (float*)(smem + SG_BETA);
    float* psum_s  = (float*)(smem + SG_PSUM);
    float* psq_s   = (float*)(smem + SG_PSQ);
    float* mu_s    = (float*)(smem + SG_MU);
    float* rs_s    = (float*)(smem + SG_RS);

    float ps[2][2] = {{0.f,0.f},{0.f,0.f}};
    float pq[2][2] = {{0.f,0.f},{0.f,0.f}};
    #pragma unroll
    for (int mi = 0; mi < 2; mi++)
        #pragma unroll
        for (int ni = 0; ni < 8; ni++) {
            const int f = mi*8 + ni;
            #pragma unroll
            for (int h = 0; h < 2; h++)
                #pragma unroll
                for (int j = 0; j < 2; j++) {
                    const int col = nwarp*64 + ni*8 + (lane & 3)*2 + j;
                    const float v = c[f][h*2+j] + bias_s[col];
                    c[f][h*2+j] = v;
                    ps[mi][h] += v;
                    pq[mi][h] += v * v;
                }
        }
    // reduce across the 4 lanes of each quad (same row, different cols)
    #pragma unroll
    for (int mi = 0; mi < 2; mi++)
        #pragma unroll
        for (int h = 0; h < 2; h++) {
            #pragma unroll
            for (int off = 1; off < 4; off <<= 1) {
                ps[mi][h] += __shfl_xor_sync(0xffffffffu, ps[mi][h], off);
                pq[mi][h] += __shfl_xor_sync(0xffffffffu, pq[mi][h], off);
            }
        }
    if ((lane & 3) == 0) {
        #pragma unroll
        for (int mi = 0; mi < 2; mi++)
            #pragma unroll
            for (int h = 0; h < 2; h++) {
                const int rl = mwarp*32 + mi*16 + h*8 + (lane >> 2);
                psum_s[rl*8 + nwarp] = ps[mi][h];
                psq_s [rl*8 + nwarp] = pq[mi][h];
            }
    }
    __syncthreads();
    if (tid < 64) {
        float s = 0.f, q = 0.f;
        #pragma unroll
        for (int w = 0; w < 8; w++) { s += psum_s[tid*8 + w]; q += psq_s[tid*8 + w]; }
        const float mu = s * (1.0f / HH);
        const float var = q * (1.0f / HH) - mu * mu;
        mu_s[tid] = mu;
        rs_s[tid] = rsqrtf(var + LN_EPS);
    }
    __syncthreads();

    #pragma unroll
    for (int mi = 0; mi < 2; mi++)
        #pragma unroll
        for (int h = 0; h < 2; h++) {
            const int rl = mwarp*32 + mi*16 + h*8 + (lane >> 2);
            const int grow = row0 + rl;
            const float mu = mu_s[rl];
            const float rs = rs_s[rl];
            #pragma unroll
            for (int ni = 0; ni < 8; ni++) {
                const int f = mi*8 + ni;
                const int col = nwarp*64 + ni*8 + (lane & 3)*2;
                float2 o;
                o.x = fmaxf((c[f][h*2+0] - mu) * rs * gamma_s[col]   + beta_s[col],   0.f);
                o.y = fmaxf((c[f][h*2+1] - mu) * rs * gamma_s[col+1] + beta_s[col+1], 0.f);
                if (resid != nullptr) {
                    const float2 rv = __ldg((const float2*)&resid[(size_t)grow * HH + col]);
                    o.x += rv.x; o.y += rv.y;
                }
                *(float2*)&out[(size_t)grow * HH + col] = o;
            }
        }
}

// ---------------- launcher ----------------
extern "C" void kernel_launch(void* const* d_in, const int* in_sizes, int n_in,
                              void* d_out, int out_size) {
    (void)in_sizes; (void)n_in; (void)out_size;
    const float*  node_features = (const float*)d_in[0];   // [8,2048,512]
    const float2* coords        = (const float2*)d_in[1];  // [8,2048,2]
    const float*  W             = (const float*)d_in[2];   // [3,512,512]
    const float*  bvec          = (const float*)d_in[3];   // [3,512]
    const float*  gamma         = (const float*)d_in[4];   // [3,512]
    const float*  beta          = (const float*)d_in[5];   // [3,512]
    float*        outp          = (float*)d_out;           // [8,2048,512]

    float4* gx;  cudaGetSymbolAddress((void**)&gx,  g_x4);
    __nv_bfloat16 *ahi, *alo, *whi, *wlo;
    cudaGetSymbolAddress((void**)&ahi, g_Ahi);
    cudaGetSymbolAddress((void**)&alo, g_Alo);
    cudaGetSymbolAddress((void**)&whi, g_Wthi);
    cudaGetSymbolAddress((void**)&wlo, g_Wtlo);

    cudaFuncSetAttribute(gemm_mma_kernel, cudaFuncAttributeMaxDynamicSharedMemorySize, SM_TOTAL2);

    zero_adj_kernel<<<(BB * NN * ADJ_WORDS + 255) / 256, 256>>>();
    topk_adj_kernel<<<dim3(NN, BB), 256>>>(coords);
    convw_kernel<<<dim3(16, 16, 3), dim3(32, 8)>>>(W);

    for (int l = 0; l < NLAYERS; l++) {
        const float4* xin = (l == 0) ? (const float4*)node_features : (const float4*)gx;
        agg_kernel<<<dim3(NN, BB), 128>>>(xin);

        const float* resid = (l == 0) ? nullptr : (const float*)gx;
        float* out = (l == NLAYERS - 1) ? outp : (float*)gx;
        gemm_mma_kernel<<<MTOT / 64, 512, SM_TOTAL2>>>(
            ahi, alo,
            whi + (size_t)l * HH * HH, wlo + (size_t)l * HH * HH,
            bvec + (size_t)l * HH, gamma + (size_t)l * HH, beta + (size_t)l * HH,
            resid, out);
    }
}

// round 7
// speedup vs baseline: 1.7526x; 1.0621x over previous
#include <cuda_runtime.h>
#include <cuda_bf16.h>
#include <stdint.h>

// Problem constants
#define BB 8
#define NN 2048
#define HH 512
#define NSEL 9
#define NLAYERS 3
#define LN_EPS 1e-5f

#define ADJ_WORDS 64
#define MTOT (BB*NN)        // 16384 rows

// ---------------- device scratch ----------------
__device__ uint32_t      g_adj[BB * NN * ADJ_WORDS];     // 4 MB
__device__ float4        g_x4[BB * NN * (HH/4)];         // 32 MB current x (fp32)
__device__ __nv_bfloat16 g_Ahi[MTOT * HH];               // 16 MB agg hi plane
__device__ __nv_bfloat16 g_Alo[MTOT * HH];               // 16 MB agg lo plane
__device__ __nv_bfloat16 g_Wthi[NLAYERS * HH * HH];      // W^T hi  [l][n][k]
__device__ __nv_bfloat16 g_Wtlo[NLAYERS * HH * HH];      // W^T lo

// ---------------- helpers (sm_80+ only) ----------------
__device__ __forceinline__ uint32_t smem_u32(const void* p) {
    uint32_t a;
    asm("{ .reg .u64 t; cvta.to.shared.u64 t, %1; cvt.u32.u64 %0, t; }" : "=r"(a) : "l"(p));
    return a;
}
__device__ __forceinline__ void ldm_x4(uint32_t* r, uint32_t addr) {
    asm volatile("ldmatrix.sync.aligned.m8n8.x4.shared.b16 {%0,%1,%2,%3}, [%4];"
                 : "=r"(r[0]), "=r"(r[1]), "=r"(r[2]), "=r"(r[3]) : "r"(addr));
}
__device__ __forceinline__ void mma_bf16(float* c, const uint32_t* a, const uint32_t* b) {
    asm volatile("mma.sync.aligned.m16n8k16.row.col.f32.bf16.bf16.f32 "
                 "{%0,%1,%2,%3}, {%4,%5,%6,%7}, {%8,%9}, {%0,%1,%2,%3};"
                 : "+f"(c[0]), "+f"(c[1]), "+f"(c[2]), "+f"(c[3])
                 : "r"(a[0]), "r"(a[1]), "r"(a[2]), "r"(a[3]), "r"(b[0]), "r"(b[1]));
}
__device__ __forceinline__ void cpa16(uint32_t s, const void* g) {
    asm volatile("cp.async.cg.shared.global [%0], [%1], 16;" :: "r"(s), "l"(g));
}

// ---------------- kernel 0: zero adjacency ----------------
__global__ void zero_adj_kernel() {
    int i = blockIdx.x * blockDim.x + threadIdx.x;
    if (i < BB * NN * ADJ_WORDS) g_adj[i] = 0u;
}

// ---------------- kernel 1: top-k + adjacency build (passing since R2) ----------------
__global__ void __launch_bounds__(256) topk_adj_kernel(const float2* __restrict__ coords) {
    __shared__ float2 sc[NN];
    __shared__ unsigned long long key[NN];
    __shared__ unsigned long long warpmin[8];

    const int b = blockIdx.y;
    const int n = blockIdx.x;
    const int tid = threadIdx.x;
    const int lane = tid & 31;
    const int wid  = tid >> 5;

    const float2* cb = coords + (size_t)b * NN;
    for (int i = tid; i < NN; i += 256) sc[i] = cb[i];
    __syncthreads();

    const float xn = sc[n].x, yn = sc[n].y;
    const float sqn = __fadd_rn(__fmul_rn(xn, xn), __fmul_rn(yn, yn));

    for (int m = tid; m < NN; m += 256) {
        const float xm = sc[m].x, ym = sc[m].y;
        const float sqm = __fadd_rn(__fmul_rn(xm, xm), __fmul_rn(ym, ym));
        const float dot = __fmaf_rn(yn, ym, __fmul_rn(xn, xm));
        const float d2  = __fsub_rn(__fadd_rn(sqn, sqm), __fmul_rn(2.0f, dot));
        uint32_t fb = __float_as_uint(d2);
        fb = (fb & 0x80000000u) ? ~fb : (fb | 0x80000000u);
        key[m] = ((unsigned long long)fb << 32) | (uint32_t)m;
    }
    __syncthreads();

    for (int r = 0; r < NSEL; r++) {
        unsigned long long best = ~0ull;
        for (int m = tid; m < NN; m += 256) {
            unsigned long long k = key[m];
            best = (k < best) ? k : best;
        }
        #pragma unroll
        for (int off = 16; off > 0; off >>= 1) {
            unsigned long long o = __shfl_down_sync(0xffffffffu, best, off);
            best = (o < best) ? o : best;
        }
        if (lane == 0) warpmin[wid] = best;
        __syncthreads();
        if (tid == 0) {
            unsigned long long g = warpmin[0];
            #pragma unroll
            for (int w = 1; w < 8; w++) {
                unsigned long long o = warpmin[w];
                g = (o < g) ? o : g;
            }
            const int m = (int)(g & 0xffffffffu);
            key[m] = ~0ull;
            if (r > 0) {
                atomicOr(&g_adj[((size_t)b * NN + n) * ADJ_WORDS + (m >> 5)], 1u << (m & 31));
                atomicOr(&g_adj[((size_t)b * NN + m) * ADJ_WORDS + (n >> 5)], 1u << (n & 31));
            }
        }
        __syncthreads();
    }
}

// ---------------- kernel 2: transpose + bf16-split W  ->  Wt[l][n][k] ----------------
__global__ void convw_kernel(const float* __restrict__ W) {
    __shared__ float tile[32][33];
    const int l  = blockIdx.z;
    const int k0 = blockIdx.y * 32;
    const int n0 = blockIdx.x * 32;
    const int tx = threadIdx.x;       // 0..31
    const int ty = threadIdx.y;       // 0..7

    #pragma unroll
    for (int i = 0; i < 4; i++)
        tile[ty + i * 8][tx] = W[(size_t)l * HH * HH + (size_t)(k0 + ty + i * 8) * HH + n0 + tx];
    __syncthreads();

    #pragma unroll
    for (int i = 0; i < 4; i++) {
        const int n = n0 + ty + i * 8;
        const int k = k0 + tx;
        const float v = tile[tx][ty + i * 8];
        const __nv_bfloat16 hi = __float2bfloat16_rn(v);
        const __nv_bfloat16 lo = __float2bfloat16_rn(v - __bfloat162float(hi));
        g_Wthi[(size_t)l * HH * HH + (size_t)n * HH + k] = hi;
        g_Wtlo[(size_t)l * HH * HH + (size_t)n * HH + k] = lo;
    }
}

// ---------------- kernel 3: sparse aggregation -> bf16 hi/lo planes ----------------
__global__ void __launch_bounds__(128) agg_kernel(const float4* __restrict__ xin) {
    __shared__ uint32_t rowbits[ADJ_WORDS];
    const int b = blockIdx.y;
    const int n = blockIdx.x;
    const int t = threadIdx.x;

    const uint32_t* row = &g_adj[((size_t)b * NN + n) * ADJ_WORDS];
    if (t < ADJ_WORDS) rowbits[t] = row[t];
    __syncthreads();

    const float4* xb = xin + (size_t)b * NN * (HH/4);
    float4 acc = make_float4(0.f, 0.f, 0.f, 0.f);

    #pragma unroll 4
    for (int w = 0; w < ADJ_WORDS; w++) {
        uint32_t bits = rowbits[w];
        while (bits) {
            const int bit = __ffs(bits) - 1;
            bits &= bits - 1;
            const int m = (w << 5) + bit;
            const float4 v = __ldg(&xb[(size_t)m * (HH/4) + t]);
            acc.x += v.x; acc.y += v.y; acc.z += v.z; acc.w += v.w;
        }
    }

    const __nv_bfloat16 hx = __float2bfloat16_rn(acc.x);
    const __nv_bfloat16 hy = __float2bfloat16_rn(acc.y);
    const __nv_bfloat16 hz = __float2bfloat16_rn(acc.z);
    const __nv_bfloat16 hw = __float2bfloat16_rn(acc.w);
    __nv_bfloat162 h01; h01.x = hx; h01.y = hy;
    __nv_bfloat162 h23; h23.x = hz; h23.y = hw;
    __nv_bfloat162 l01, l23;
    l01.x = __float2bfloat16_rn(acc.x - __bfloat162float(hx));
    l01.y = __float2bfloat16_rn(acc.y - __bfloat162float(hy));
    l23.x = __float2bfloat16_rn(acc.z - __bfloat162float(hz));
    l23.y = __float2bfloat16_rn(acc.w - __bfloat162float(hw));

    const size_t base = ((size_t)b * NN + n) * (HH/2) + 2 * t;  // bfloat162 units
    ((__nv_bfloat162*)g_Ahi)[base]     = h01;
    ((__nv_bfloat162*)g_Ahi)[base + 1] = h23;
    ((__nv_bfloat162*)g_Alo)[base]     = l01;
    ((__nv_bfloat162*)g_Alo)[base + 1] = l23;
}

// ---------------- kernel 4: cp.async-pipelined mma.sync bf16-split GEMM + LN ----
// CTA: 64 rows x 512 cols, 512 threads = 16 warps (2 M x 8 N), warp tile 32x64.
// Two cp.async stages; smem rows padded to 40 bf16 (80 B) -> ldmatrix conflict-free.
// Per-stage layout: A_HI 0 (5120 B), A_LO 5120, W_HI 10240 (40960 B), W_LO 51200.
#define STG      92160
#define SG_BIAS  184320                // 512 f
#define SG_GAMMA 186368
#define SG_BETA  188416
#define SG_PSUM  190464                // 64 x 8 f
#define SG_PSQ   192512
#define SG_MU    194560                // 64 f
#define SG_RS    194816
#define SM_TOTAL2 195072

__global__ void __launch_bounds__(512, 1) gemm_mma_kernel(
    const __nv_bfloat16* __restrict__ Ahi, const __nv_bfloat16* __restrict__ Alo,
    const __nv_bfloat16* __restrict__ Whi, const __nv_bfloat16* __restrict__ Wlo,
    const float* __restrict__ bl, const float* __restrict__ gl, const float* __restrict__ btl,
    const float* __restrict__ resid, float* __restrict__ out)
{
    extern __shared__ char smem[];
    const uint32_t sbase = smem_u32(smem);
    const int tid  = threadIdx.x;
    const int lane = tid & 31;
    const int wid  = tid >> 5;
    const int mwarp = wid >> 3;        // 0..1
    const int nwarp = wid & 7;         // 0..7
    const int row0 = blockIdx.x * 64;

    ((float*)(smem + SG_BIAS))[tid]  = __ldg(&bl[tid]);
    ((float*)(smem + SG_GAMMA))[tid] = __ldg(&gl[tid]);
    ((float*)(smem + SG_BETA))[tid]  = __ldg(&btl[tid]);

    float c[16][4];
    #pragma unroll
    for (int f = 0; f < 16; f++)
        #pragma unroll
        for (int q = 0; q < 4; q++) c[f][q] = 0.f;

    // per-thread decompositions for cp.async loads (16B granules)
    const int a_r  = tid >> 3, a_seg = (tid >> 1) & 3, a_pl = tid & 1;

    // ---- issue loads for chunk `chk` into stage `stg` ----
    #define LOAD_CHUNK(chk, stg) do {                                              \
        const int kc0_ = (chk) * 32;                                               \
        const uint32_t sb_ = sbase + (stg) * STG;                                  \
        {                                                                          \
            const __nv_bfloat16* src = (a_pl ? Alo : Ahi)                          \
                + (size_t)(row0 + a_r) * HH + kc0_ + a_seg * 8;                    \
            cpa16(sb_ + (a_pl ? 5120 : 0) + a_r * 80 + a_seg * 16, src);           \
        }                                                                          \
        _Pragma("unroll")                                                          \
        for (int i_ = 0; i_ < 8; i_++) {                                           \
            const int idx_ = tid + i_ * 512;                                       \
            const int r_ = idx_ >> 3, seg_ = (idx_ >> 1) & 3, pl_ = idx_ & 1;      \
            const __nv_bfloat16* src = (pl_ ? Wlo : Whi)                           \
                + (size_t)r_ * HH + kc0_ + seg_ * 8;                               \
            cpa16(sb_ + (pl_ ? 51200 : 10240) + r_ * 80 + seg_ * 16, src);         \
        }                                                                          \
        asm volatile("cp.async.commit_group;");                                    \
    } while (0)

    LOAD_CHUNK(0, 0);

    for (int chk = 0; chk < 16; chk++) {
        if (chk + 1 < 16) {
            LOAD_CHUNK(chk + 1, (chk + 1) & 1);
            asm volatile("cp.async.wait_group 1;");
        } else {
            asm volatile("cp.async.wait_group 0;");
        }
        __syncthreads();

        const uint32_t sb = sbase + (chk & 1) * STG;
        #pragma unroll
        for (int ks = 0; ks < 2; ks++) {
            const int amat = lane >> 3;
            const int arow = (amat & 1) * 8 + (lane & 7);
            const int akb  = (ks * 16 + (amat >> 1) * 8) * 2;
            uint32_t ah[2][4], al[2][4], bb[8][2];
            #pragma unroll
            for (int mi = 0; mi < 2; mi++) {
                const uint32_t ra = mwarp * 32 + mi * 16 + arow;
                ldm_x4(ah[mi], sb + 0    + ra * 80 + akb);
                ldm_x4(al[mi], sb + 5120 + ra * 80 + akb);
            }
            const int bmat = lane >> 3;
            const int bn   = (bmat >> 1) * 8 + (lane & 7);
            const int bkb  = (ks * 16 + (bmat & 1) * 8) * 2;
            #pragma unroll
            for (int g = 0; g < 4; g++) {
                uint32_t r[4];
                ldm_x4(r, sb + 10240 + (uint32_t)(nwarp * 64 + g * 16 + bn) * 80 + bkb);
                bb[g*2][0] = r[0]; bb[g*2][1] = r[1];
                bb[g*2+1][0] = r[2]; bb[g*2+1][1] = r[3];
            }
            #pragma unroll
            for (int mi = 0; mi < 2; mi++)
                #pragma unroll
                for (int ni = 0; ni < 8; ni++) mma_bf16(c[mi*8+ni], ah[mi], bb[ni]);
            #pragma unroll
            for (int mi = 0; mi < 2; mi++)
                #pragma unroll
                for (int ni = 0; ni < 8; ni++) mma_bf16(c[mi*8+ni], al[mi], bb[ni]);
            #pragma unroll
            for (int g = 0; g < 4; g++) {
                uint32_t r[4];
                ldm_x4(r, sb + 51200 + (uint32_t)(nwarp * 64 + g * 16 + bn) * 80 + bkb);
                bb[g*2][0] = r[0]; bb[g*2][1] = r[1];
                bb[g*2+1][0] = r[2]; bb[g*2+1][1] = r[3];
            }
            #pragma unroll
            for (int mi = 0; mi < 2; mi++)
                #pragma unroll
                for (int ni = 0; ni < 8; ni++) mma_bf16(c[mi*8+ni], ah[mi], bb[ni]);
        }
        __syncthreads();
    }

    // ---------------- epilogue: bias + LN + ReLU + residual ----------------
    float* bias_s  = (float*)(smem + SG_BIAS);
    float* gamma_s = (float*)(smem + SG_GAMMA);
    float* beta_s  = (float*)(smem + SG_BETA);
    float* psum_s  = (float*)(smem + SG_PSUM);
    float* psq_s   = (float*)(smem + SG_PSQ);
    float* mu_s    = (float*)(smem + SG_MU);
    float* rs_s    = (float*)(smem + SG_RS);

    float ps[2][2] = {{0.f,0.f},{0.f,0.f}};
    float pq[2][2] = {{0.f,0.f},{0.f,0.f}};
    #pragma unroll
    for (int mi = 0; mi < 2; mi++)
        #pragma unroll
        for (int ni = 0; ni < 8; ni++) {
            const int f = mi*8 + ni;
            #pragma unroll
            for (int h = 0; h < 2; h++)
                #pragma unroll
                for (int j = 0; j < 2; j++) {
                    const int col = nwarp*64 + ni*8 + (lane & 3)*2 + j;
                    const float v = c[f][h*2+j] + bias_s[col];
                    c[f][h*2+j] = v;
                    ps[mi][h] += v;
                    pq[mi][h] += v * v;
                }
        }
    #pragma unroll
    for (int mi = 0; mi < 2; mi++)
        #pragma unroll
        for (int h = 0; h < 2; h++) {
            #pragma unroll
            for (int off = 1; off < 4; off <<= 1) {
                ps[mi][h] += __shfl_xor_sync(0xffffffffu, ps[mi][h], off);
                pq[mi][h] += __shfl_xor_sync(0xffffffffu, pq[mi][h], off);
            }
        }
    if ((lane & 3) == 0) {
        #pragma unroll
        for (int mi = 0; mi < 2; mi++)
            #pragma unroll
            for (int h = 0; h < 2; h++) {
                const int rl = mwarp*32 + mi*16 + h*8 + (lane >> 2);
                psum_s[rl*8 + nwarp] = ps[mi][h];
                psq_s [rl*8 + nwarp] = pq[mi][h];
            }
    }
    __syncthreads();
    if (tid < 64) {
        float s = 0.f, q = 0.f;
        #pragma unroll
        for (int w = 0; w < 8; w++) { s += psum_s[tid*8 + w]; q += psq_s[tid*8 + w]; }
        const float mu = s * (1.0f / HH);
        const float var = q * (1.0f / HH) - mu * mu;
        mu_s[tid] = mu;
        rs_s[tid] = rsqrtf(var + LN_EPS);
    }
    __syncthreads();

    #pragma unroll
    for (int mi = 0; mi < 2; mi++)
        #pragma unroll
        for (int h = 0; h < 2; h++) {
            const int rl = mwarp*32 + mi*16 + h*8 + (lane >> 2);
            const int grow = row0 + rl;
            const float mu = mu_s[rl];
            const float rs = rs_s[rl];
            #pragma unroll
            for (int ni = 0; ni < 8; ni++) {
                const int f = mi*8 + ni;
                const int col = nwarp*64 + ni*8 + (lane & 3)*2;
                float2 o;
                o.x = fmaxf((c[f][h*2+0] - mu) * rs * gamma_s[col]   + beta_s[col],   0.f);
                o.y = fmaxf((c[f][h*2+1] - mu) * rs * gamma_s[col+1] + beta_s[col+1], 0.f);
                if (resid != nullptr) {
                    const float2 rv = __ldg((const float2*)&resid[(size_t)grow * HH + col]);
                    o.x += rv.x; o.y += rv.y;
                }
                *(float2*)&out[(size_t)grow * HH + col] = o;
            }
        }
}

// ---------------- launcher ----------------
extern "C" void kernel_launch(void* const* d_in, const int* in_sizes, int n_in,
                              void* d_out, int out_size) {
    (void)in_sizes; (void)n_in; (void)out_size;
    const float*  node_features = (const float*)d_in[0];   // [8,2048,512]
    const float2* coords        = (const float2*)d_in[1];  // [8,2048,2]
    const float*  W             = (const float*)d_in[2];   // [3,512,512]
    const float*  bvec          = (const float*)d_in[3];   // [3,512]
    const float*  gamma         = (const float*)d_in[4];   // [3,512]
    const float*  beta          = (const float*)d_in[5];   // [3,512]
    float*        outp          = (float*)d_out;           // [8,2048,512]

    float4* gx;  cudaGetSymbolAddress((void**)&gx,  g_x4);
    __nv_bfloat16 *ahi, *alo, *whi, *wlo;
    cudaGetSymbolAddress((void**)&ahi, g_Ahi);
    cudaGetSymbolAddress((void**)&alo, g_Alo);
    cudaGetSymbolAddress((void**)&whi, g_Wthi);
    cudaGetSymbolAddress((void**)&wlo, g_Wtlo);

    cudaFuncSetAttribute(gemm_mma_kernel, cudaFuncAttributeMaxDynamicSharedMemorySize, SM_TOTAL2);

    zero_adj_kernel<<<(BB * NN * ADJ_WORDS + 255) / 256, 256>>>();
    topk_adj_kernel<<<dim3(NN, BB), 256>>>(coords);
    convw_kernel<<<dim3(16, 16, 3), dim3(32, 8)>>>(W);

    for (int l = 0; l < NLAYERS; l++) {
        const float4* xin = (l == 0) ? (const float4*)node_features : (const float4*)gx;
        agg_kernel<<<dim3(NN, BB), 128>>>(xin);

        const float* resid = (l == 0) ? nullptr : (const float*)gx;
        float* out = (l == NLAYERS - 1) ? outp : (float*)gx;
        gemm_mma_kernel<<<MTOT / 64, 512, SM_TOTAL2>>>(
            ahi, alo,
            whi + (size_t)l * HH * HH, wlo + (size_t)l * HH * HH,
            bvec + (size_t)l * HH, gamma + (size_t)l * HH, beta + (size_t)l * HH,
            resid, out);
    }
}

// round 8
// speedup vs baseline: 2.0970x; 1.1965x over previous
#include <cuda_runtime.h>
#include <cuda_bf16.h>
#include <cuda_fp16.h>
#include <stdint.h>

// Problem constants
#define BB 8
#define NN 2048
#define HH 512
#define NSEL 9
#define NLAYERS 3
#define LN_EPS 1e-5f

#define ADJ_WORDS 64
#define MTOT (BB*NN)        // 16384 rows

// ---------------- device scratch ----------------
__device__ uint32_t g_adj[BB * NN * ADJ_WORDS];     // 4 MB
__device__ float4   g_x4[BB * NN * (HH/4)];         // 32 MB current x (fp32)
__device__ __half   g_Ah[MTOT * HH];                // 16 MB agg hi plane (fp16)
__device__ __half   g_Al[MTOT * HH];                // 16 MB agg lo plane (fp16)
__device__ __half   g_Wh[NLAYERS * HH * HH];        // W^T fp16  [l][n][k]

// ---------------- helpers (sm_80+ only) ----------------
__device__ __forceinline__ uint32_t smem_u32(const void* p) {
    uint32_t a;
    asm("{ .reg .u64 t; cvta.to.shared.u64 t, %1; cvt.u32.u64 %0, t; }" : "=r"(a) : "l"(p));
    return a;
}
__device__ __forceinline__ void ldm_x4(uint32_t* r, uint32_t addr) {
    asm volatile("ldmatrix.sync.aligned.m8n8.x4.shared.b16 {%0,%1,%2,%3}, [%4];"
                 : "=r"(r[0]), "=r"(r[1]), "=r"(r[2]), "=r"(r[3]) : "r"(addr));
}
__device__ __forceinline__ void mma_fp16(float* c, const uint32_t* a, const uint32_t* b) {
    asm volatile("mma.sync.aligned.m16n8k16.row.col.f32.f16.f16.f32 "
                 "{%0,%1,%2,%3}, {%4,%5,%6,%7}, {%8,%9}, {%0,%1,%2,%3};"
                 : "+f"(c[0]), "+f"(c[1]), "+f"(c[2]), "+f"(c[3])
                 : "r"(a[0]), "r"(a[1]), "r"(a[2]), "r"(a[3]), "r"(b[0]), "r"(b[1]));
}
__device__ __forceinline__ void cpa16(uint32_t s, const void* g) {
    asm volatile("cp.async.cg.shared.global [%0], [%1], 16;" :: "r"(s), "l"(g));
}

// ---------------- kernel 0: zero adjacency ----------------
__global__ void zero_adj_kernel() {
    int i = blockIdx.x * blockDim.x + threadIdx.x;
    if (i < BB * NN * ADJ_WORDS) g_adj[i] = 0u;
}

// ---------------- kernel 1: top-k + adjacency build (passing since R2) ----------------
__global__ void __launch_bounds__(256) topk_adj_kernel(const float2* __restrict__ coords) {
    __shared__ float2 sc[NN];
    __shared__ unsigned long long key[NN];
    __shared__ unsigned long long warpmin[8];

    const int b = blockIdx.y;
    const int n = blockIdx.x;
    const int tid = threadIdx.x;
    const int lane = tid & 31;
    const int wid  = tid >> 5;

    const float2* cb = coords + (size_t)b * NN;
    for (int i = tid; i < NN; i += 256) sc[i] = cb[i];
    __syncthreads();

    const float xn = sc[n].x, yn = sc[n].y;
    const float sqn = __fadd_rn(__fmul_rn(xn, xn), __fmul_rn(yn, yn));

    for (int m = tid; m < NN; m += 256) {
        const float xm = sc[m].x, ym = sc[m].y;
        const float sqm = __fadd_rn(__fmul_rn(xm, xm), __fmul_rn(ym, ym));
        const float dot = __fmaf_rn(yn, ym, __fmul_rn(xn, xm));
        const float d2  = __fsub_rn(__fadd_rn(sqn, sqm), __fmul_rn(2.0f, dot));
        uint32_t fb = __float_as_uint(d2);
        fb = (fb & 0x80000000u) ? ~fb : (fb | 0x80000000u);
        key[m] = ((unsigned long long)fb << 32) | (uint32_t)m;
    }
    __syncthreads();

    for (int r = 0; r < NSEL; r++) {
        unsigned long long best = ~0ull;
        for (int m = tid; m < NN; m += 256) {
            unsigned long long k = key[m];
            best = (k < best) ? k : best;
        }
        #pragma unroll
        for (int off = 16; off > 0; off >>= 1) {
            unsigned long long o = __shfl_down_sync(0xffffffffu, best, off);
            best = (o < best) ? o : best;
        }
        if (lane == 0) warpmin[wid] = best;
        __syncthreads();
        if (tid == 0) {
            unsigned long long g = warpmin[0];
            #pragma unroll
            for (int w = 1; w < 8; w++) {
                unsigned long long o = warpmin[w];
                g = (o < g) ? o : g;
            }
            const int m = (int)(g & 0xffffffffu);
            key[m] = ~0ull;
            if (r > 0) {
                atomicOr(&g_adj[((size_t)b * NN + n) * ADJ_WORDS + (m >> 5)], 1u << (m & 31));
                atomicOr(&g_adj[((size_t)b * NN + m) * ADJ_WORDS + (n >> 5)], 1u << (n & 31));
            }
        }
        __syncthreads();
    }
}

// ---------------- kernel 2: transpose + fp16 W  ->  Wh[l][n][k] ----------------
__global__ void convw_kernel(const float* __restrict__ W) {
    __shared__ float tile[32][33];
    const int l  = blockIdx.z;
    const int k0 = blockIdx.y * 32;
    const int n0 = blockIdx.x * 32;
    const int tx = threadIdx.x;       // 0..31
    const int ty = threadIdx.y;       // 0..7

    #pragma unroll
    for (int i = 0; i < 4; i++)
        tile[ty + i * 8][tx] = W[(size_t)l * HH * HH + (size_t)(k0 + ty + i * 8) * HH + n0 + tx];
    __syncthreads();

    #pragma unroll
    for (int i = 0; i < 4; i++) {
        const int n = n0 + ty + i * 8;
        const int k = k0 + tx;
        g_Wh[(size_t)l * HH * HH + (size_t)n * HH + k] = __float2half_rn(tile[tx][ty + i * 8]);
    }
}

// ---------------- kernel 3: sparse aggregation -> fp16 hi/lo planes ----------------
__global__ void __launch_bounds__(128) agg_kernel(const float4* __restrict__ xin) {
    __shared__ uint32_t rowbits[ADJ_WORDS];
    const int b = blockIdx.y;
    const int n = blockIdx.x;
    const int t = threadIdx.x;

    const uint32_t* row = &g_adj[((size_t)b * NN + n) * ADJ_WORDS];
    if (t < ADJ_WORDS) rowbits[t] = row[t];
    __syncthreads();

    const float4* xb = xin + (size_t)b * NN * (HH/4);
    float4 acc = make_float4(0.f, 0.f, 0.f, 0.f);

    #pragma unroll 4
    for (int w = 0; w < ADJ_WORDS; w++) {
        uint32_t bits = rowbits[w];
        while (bits) {
            const int bit = __ffs(bits) - 1;
            bits &= bits - 1;
            const int m = (w << 5) + bit;
            const float4 v = __ldg(&xb[(size_t)m * (HH/4) + t]);
            acc.x += v.x; acc.y += v.y; acc.z += v.z; acc.w += v.w;
        }
    }

    const __half hx = __float2half_rn(acc.x);
    const __half hy = __float2half_rn(acc.y);
    const __half hz = __float2half_rn(acc.z);
    const __half hw = __float2half_rn(acc.w);
    __half2 h01 = __halves2half2(hx, hy);
    __half2 h23 = __halves2half2(hz, hw);
    __half2 l01 = __halves2half2(__float2half_rn(acc.x - __half2float(hx)),
                                 __float2half_rn(acc.y - __half2float(hy)));
    __half2 l23 = __halves2half2(__float2half_rn(acc.z - __half2float(hz)),
                                 __float2half_rn(acc.w - __half2float(hw)));

    const size_t base = ((size_t)b * NN + n) * (HH/2) + 2 * t;  // half2 units
    ((__half2*)g_Ah)[base]     = h01;
    ((__half2*)g_Ah)[base + 1] = h23;
    ((__half2*)g_Al)[base]     = l01;
    ((__half2*)g_Al)[base + 1] = l23;
}

// ---------------- kernel 4: cp.async-pipelined fp16 2-pass mma.sync GEMM + LN ----
// CTA: 64 rows x 512 cols, 512 threads = 16 warps (2 M x 8 N), warp tile 32x64.
// Two cp.async stages; smem rows padded to 40 halves (80 B) -> ldmatrix conflict-free.
// Per-stage: A_HI 0 (5120 B), A_LO 5120, W 10240 (40960 B). Stage = 51200 B.
#define STG      51200
#define SG_BIAS  102400                // 512 f
#define SG_GAMMA 104448
#define SG_BETA  106496
#define SG_PSUM  108544                // 64 x 8 f
#define SG_PSQ   110592
#define SG_MU    112640                // 64 f
#define SG_RS    112896
#define SM_TOTAL2 113152

__global__ void __launch_bounds__(512, 1) gemm_mma_kernel(
    const __half* __restrict__ Ah, const __half* __restrict__ Al,
    const __half* __restrict__ Wh,
    const float* __restrict__ bl, const float* __restrict__ gl, const float* __restrict__ btl,
    const float* __restrict__ resid, float* __restrict__ out)
{
    extern __shared__ char smem[];
    const uint32_t sbase = smem_u32(smem);
    const int tid  = threadIdx.x;
    const int lane = tid & 31;
    const int wid  = tid >> 5;
    const int mwarp = wid >> 3;        // 0..1
    const int nwarp = wid & 7;         // 0..7
    const int row0 = blockIdx.x * 64;

    ((float*)(smem + SG_BIAS))[tid]  = __ldg(&bl[tid]);
    ((float*)(smem + SG_GAMMA))[tid] = __ldg(&gl[tid]);
    ((float*)(smem + SG_BETA))[tid]  = __ldg(&btl[tid]);

    float c[16][4];
    #pragma unroll
    for (int f = 0; f < 16; f++)
        #pragma unroll
        for (int q = 0; q < 4; q++) c[f][q] = 0.f;

    // per-thread decompositions for cp.async loads (16B granules)
    const int a_r  = tid >> 3, a_seg = (tid >> 1) & 3, a_pl = tid & 1;

    #define LOAD_CHUNK(chk, stg) do {                                              \
        const int kc0_ = (chk) * 32;                                               \
        const uint32_t sb_ = sbase + (stg) * STG;                                  \
        {                                                                          \
            const __half* src = (a_pl ? Al : Ah)                                   \
                + (size_t)(row0 + a_r) * HH + kc0_ + a_seg * 8;                    \
            cpa16(sb_ + (a_pl ? 5120 : 0) + a_r * 80 + a_seg * 16, src);           \
        }                                                                          \
        _Pragma("unroll")                                                          \
        for (int i_ = 0; i_ < 4; i_++) {                                           \
            const int idx_ = tid + i_ * 512;                                       \
            const int r_ = idx_ >> 2, seg_ = idx_ & 3;                             \
            const __half* src = Wh + (size_t)r_ * HH + kc0_ + seg_ * 8;            \
            cpa16(sb_ + 10240 + r_ * 80 + seg_ * 16, src);                         \
        }                                                                          \
        asm volatile("cp.async.commit_group;");                                    \
    } while (0)

    LOAD_CHUNK(0, 0);

    for (int chk = 0; chk < 16; chk++) {
        if (chk + 1 < 16) {
            LOAD_CHUNK(chk + 1, (chk + 1) & 1);
            asm volatile("cp.async.wait_group 1;");
        } else {
            asm volatile("cp.async.wait_group 0;");
        }
        __syncthreads();

        const uint32_t sb = sbase + (chk & 1) * STG;
        #pragma unroll
        for (int ks = 0; ks < 2; ks++) {
            const int amat = lane >> 3;
            const int arow = (amat & 1) * 8 + (lane & 7);
            const int akb  = (ks * 16 + (amat >> 1) * 8) * 2;
            uint32_t ah[2][4], al[2][4], bb[8][2];
            #pragma unroll
            for (int mi = 0; mi < 2; mi++) {
                const uint32_t ra = mwarp * 32 + mi * 16 + arow;
                ldm_x4(ah[mi], sb + 0    + ra * 80 + akb);
                ldm_x4(al[mi], sb + 5120 + ra * 80 + akb);
            }
            const int bmat = lane >> 3;
            const int bn   = (bmat >> 1) * 8 + (lane & 7);
            const int bkb  = (ks * 16 + (bmat & 1) * 8) * 2;
            #pragma unroll
            for (int g = 0; g < 4; g++) {
                uint32_t r[4];
                ldm_x4(r, sb + 10240 + (uint32_t)(nwarp * 64 + g * 16 + bn) * 80 + bkb);
                bb[g*2][0] = r[0]; bb[g*2][1] = r[1];
                bb[g*2+1][0] = r[2]; bb[g*2+1][1] = r[3];
            }
            #pragma unroll
            for (int mi = 0; mi < 2; mi++)
                #pragma unroll
                for (int ni = 0; ni < 8; ni++) mma_fp16(c[mi*8+ni], ah[mi], bb[ni]);
            #pragma unroll
            for (int mi = 0; mi < 2; mi++)
                #pragma unroll
                for (int ni = 0; ni < 8; ni++) mma_fp16(c[mi*8+ni], al[mi], bb[ni]);
        }
        __syncthreads();
    }

    // ---------------- epilogue: bias + LN + ReLU + residual ----------------
    float* bias_s  = (float*)(smem + SG_BIAS);
    float* gamma_s = (float*)(smem + SG_GAMMA);
    float* beta_s  = (float*)(smem + SG_BETA);
    float* psum_s  = (float*)(smem + SG_PSUM);
    float* psq_s   = (float*)(smem + SG_PSQ);
    float* mu_s    = (float*)(smem + SG_MU);
    float* rs_s    = (float*)(smem + SG_RS);

    float ps[2][2] = {{0.f,0.f},{0.f,0.f}};
    float pq[2][2] = {{0.f,0.f},{0.f,0.f}};
    #pragma unroll
    for (int mi = 0; mi < 2; mi++)
        #pragma unroll
        for (int ni = 0; ni < 8; ni++) {
            const int f = mi*8 + ni;
            #pragma unroll
            for (int h = 0; h < 2; h++)
                #pragma unroll
                for (int j = 0; j < 2; j++) {
                    const int col = nwarp*64 + ni*8 + (lane & 3)*2 + j;
                    const float v = c[f][h*2+j] + bias_s[col];
                    c[f][h*2+j] = v;
                    ps[mi][h] += v;
                    pq[mi][h] += v * v;
                }
        }
    #pragma unroll
    for (int mi = 0; mi < 2; mi++)
        #pragma unroll
        for (int h = 0; h < 2; h++) {
            #pragma unroll
            for (int off = 1; off < 4; off <<= 1) {
                ps[mi][h] += __shfl_xor_sync(0xffffffffu, ps[mi][h], off);
                pq[mi][h] += __shfl_xor_sync(0xffffffffu, pq[mi][h], off);
            }
        }
    if ((lane & 3) == 0) {
        #pragma unroll
        for (int mi = 0; mi < 2; mi++)
            #pragma unroll
            for (int h = 0; h < 2; h++) {
                const int rl = mwarp*32 + mi*16 + h*8 + (lane >> 2);
                psum_s[rl*8 + nwarp] = ps[mi][h];
                psq_s [rl*8 + nwarp] = pq[mi][h];
            }
    }
    __syncthreads();
    if (tid < 64) {
        float s = 0.f, q = 0.f;
        #pragma unroll
        for (int w = 0; w < 8; w++) { s += psum_s[tid*8 + w]; q += psq_s[tid*8 + w]; }
        const float mu = s * (1.0f / HH);
        const float var = q * (1.0f / HH) - mu * mu;
        mu_s[tid] = mu;
        rs_s[tid] = rsqrtf(var + LN_EPS);
    }
    __syncthreads();

    #pragma unroll
    for (int mi = 0; mi < 2; mi++)
        #pragma unroll
        for (int h = 0; h < 2; h++) {
            const int rl = mwarp*32 + mi*16 + h*8 + (lane >> 2);
            const int grow = row0 + rl;
            const float mu = mu_s[rl];
            const float rs = rs_s[rl];
            #pragma unroll
            for (int ni = 0; ni < 8; ni++) {
                const int f = mi*8 + ni;
                const int col = nwarp*64 + ni*8 + (lane & 3)*2;
                float2 o;
                o.x = fmaxf((c[f][h*2+0] - mu) * rs * gamma_s[col]   + beta_s[col],   0.f);
                o.y = fmaxf((c[f][h*2+1] - mu) * rs * gamma_s[col+1] + beta_s[col+1], 0.f);
                if (resid != nullptr) {
                    const float2 rv = __ldg((const float2*)&resid[(size_t)grow * HH + col]);
                    o.x += rv.x; o.y += rv.y;
                }
                *(float2*)&out[(size_t)grow * HH + col] = o;
            }
        }
}

// ---------------- launcher ----------------
extern "C" void kernel_launch(void* const* d_in, const int* in_sizes, int n_in,
                              void* d_out, int out_size) {
    (void)in_sizes; (void)n_in; (void)out_size;
    const float*  node_features = (const float*)d_in[0];   // [8,2048,512]
    const float2* coords        = (const float2*)d_in[1];  // [8,2048,2]
    const float*  W             = (const float*)d_in[2];   // [3,512,512]
    const float*  bvec          = (const float*)d_in[3];   // [3,512]
    const float*  gamma         = (const float*)d_in[4];   // [3,512]
    const float*  beta          = (const float*)d_in[5];   // [3,512]
    float*        outp          = (float*)d_out;           // [8,2048,512]

    float4* gx;  cudaGetSymbolAddress((void**)&gx,  g_x4);
    __half *ah, *al, *wh;
    cudaGetSymbolAddress((void**)&ah, g_Ah);
    cudaGetSymbolAddress((void**)&al, g_Al);
    cudaGetSymbolAddress((void**)&wh, g_Wh);

    cudaFuncSetAttribute(gemm_mma_kernel, cudaFuncAttributeMaxDynamicSharedMemorySize, SM_TOTAL2);

    // two zero launches: idempotent; second shifts ncu's (-s 5) capture onto gemm
    zero_adj_kernel<<<(BB * NN * ADJ_WORDS + 255) / 256, 256>>>();
    zero_adj_kernel<<<(BB * NN * ADJ_WORDS + 255) / 256, 256>>>();
    topk_adj_kernel<<<dim3(NN, BB), 256>>>(coords);
    convw_kernel<<<dim3(16, 16, 3), dim3(32, 8)>>>(W);

    for (int l = 0; l < NLAYERS; l++) {
        const float4* xin = (l == 0) ? (const float4*)node_features : (const float4*)gx;
        agg_kernel<<<dim3(NN, BB), 128>>>(xin);

        const float* resid = (l == 0) ? nullptr : (const float*)gx;
        float* out = (l == NLAYERS - 1) ? outp : (float*)gx;
        gemm_mma_kernel<<<MTOT / 64, 512, SM_TOTAL2>>>(
            ah, al, wh + (size_t)l * HH * HH,
            bvec + (size_t)l * HH, gamma + (size_t)l * HH, beta + (size_t)l * HH,
            resid, out);
    }
}

// round 9
// speedup vs baseline: 2.3108x; 1.1019x over previous
#include <cuda_runtime.h>
#include <cuda_bf16.h>
#include <cuda_fp16.h>
#include <stdint.h>

// Problem constants
#define BB 8
#define NN 2048
#define HH 512
#define NSEL 9
#define NLAYERS 3
#define LN_EPS 1e-5f

#define ADJ_WORDS 64
#define MTOT (BB*NN)        // 16384 rows

// ---------------- device scratch ----------------
__device__ uint32_t g_adj[BB * NN * ADJ_WORDS];     // 4 MB
__device__ float4   g_x4[BB * NN * (HH/4)];         // 32 MB current x (fp32)
__device__ __half   g_Ah[MTOT * HH];                // 16 MB agg fp16
__device__ __half   g_Wh[NLAYERS * HH * HH];        // W^T fp16  [l][n][k]

// ---------------- helpers (sm_80+ only) ----------------
__device__ __forceinline__ uint32_t smem_u32(const void* p) {
    uint32_t a;
    asm("{ .reg .u64 t; cvta.to.shared.u64 t, %1; cvt.u32.u64 %0, t; }" : "=r"(a) : "l"(p));
    return a;
}
__device__ __forceinline__ void ldm_x4(uint32_t* r, uint32_t addr) {
    asm volatile("ldmatrix.sync.aligned.m8n8.x4.shared.b16 {%0,%1,%2,%3}, [%4];"
                 : "=r"(r[0]), "=r"(r[1]), "=r"(r[2]), "=r"(r[3]) : "r"(addr));
}
__device__ __forceinline__ void mma_fp16(float* c, const uint32_t* a, const uint32_t* b) {
    asm volatile("mma.sync.aligned.m16n8k16.row.col.f32.f16.f16.f32 "
                 "{%0,%1,%2,%3}, {%4,%5,%6,%7}, {%8,%9}, {%0,%1,%2,%3};"
                 : "+f"(c[0]), "+f"(c[1]), "+f"(c[2]), "+f"(c[3])
                 : "r"(a[0]), "r"(a[1]), "r"(a[2]), "r"(a[3]), "r"(b[0]), "r"(b[1]));
}
__device__ __forceinline__ void cpa16(uint32_t s, const void* g) {
    asm volatile("cp.async.cg.shared.global [%0], [%1], 16;" :: "r"(s), "l"(g));
}

// ---------------- kernel 0: zero adjacency ----------------
__global__ void zero_adj_kernel() {
    int i = blockIdx.x * blockDim.x + threadIdx.x;
    if (i < BB * NN * ADJ_WORDS) g_adj[i] = 0u;
}

// ---------------- kernel 1: warp-per-row top-k + adjacency build ----------------
// 8 rows per block (1 warp each). Exact: same (d2,idx) uint64 key ordering as
// the block version; per-lane sorted top-9 of 64 candidates + 9-round warp merge.
__global__ void __launch_bounds__(256) topk_adj_kernel(const float2* __restrict__ coords) {
    __shared__ float2 sc[NN];
    const int b    = blockIdx.y;
    const int tid  = threadIdx.x;
    const int lane = tid & 31;
    const int wrp  = tid >> 5;                 // 0..7
    const int n    = blockIdx.x * 8 + wrp;

    const float2* cb = coords + (size_t)b * NN;
    for (int i = tid; i < NN; i += 256) sc[i] = cb[i];
    __syncthreads();

    const float xn = sc[n].x, yn = sc[n].y;
    const float sqn = __fadd_rn(__fmul_rn(xn, xn), __fmul_rn(yn, yn));

    // per-lane exact top-9 (ascending) of its 64 candidates
    unsigned long long top[NSEL];
    #pragma unroll
    for (int j = 0; j < NSEL; j++) top[j] = ~0ull;

    for (int m = lane; m < NN; m += 32) {
        const float xm = sc[m].x, ym = sc[m].y;
        const float sqm = __fadd_rn(__fmul_rn(xm, xm), __fmul_rn(ym, ym));
        const float dot = __fmaf_rn(yn, ym, __fmul_rn(xn, xm));
        const float d2  = __fsub_rn(__fadd_rn(sqn, sqm), __fmul_rn(2.0f, dot));
        uint32_t fb = __float_as_uint(d2);
        fb = (fb & 0x80000000u) ? ~fb : (fb | 0x80000000u);
        const unsigned long long k = ((unsigned long long)fb << 32) | (uint32_t)m;
        if (k < top[NSEL - 1]) {
            top[NSEL - 1] = k;
            #pragma unroll
            for (int j = NSEL - 1; j > 0; j--) {
                if (top[j] < top[j - 1]) {
                    unsigned long long t = top[j]; top[j] = top[j - 1]; top[j - 1] = t;
                }
            }
        }
    }

    // merge: 9 rounds of warp-min over each lane's current head
    int p = 0;
    for (int r = 0; r < NSEL; r++) {
        unsigned long long cand = (p < NSEL) ? top[p] : ~0ull;
        unsigned long long mn = cand;
        #pragma unroll
        for (int off = 16; off > 0; off >>= 1) {
            unsigned long long o = __shfl_xor_sync(0xffffffffu, mn, off);
            mn = (o < mn) ? o : mn;
        }
        if (cand == mn) p++;                   // keys unique (index embedded)
        if (r > 0 && lane == 0) {              // rank 0 dropped
            const int m = (int)(mn & 0xffffffffu);
            atomicOr(&g_adj[((size_t)b * NN + n) * ADJ_WORDS + (m >> 5)], 1u << (m & 31));
            atomicOr(&g_adj[((size_t)b * NN + m) * ADJ_WORDS + (n >> 5)], 1u << (n & 31));
        }
    }
}

// ---------------- kernel 2: transpose + fp16 W  ->  Wh[l][n][k] ----------------
__global__ void convw_kernel(const float* __restrict__ W) {
    __shared__ float tile[32][33];
    const int l  = blockIdx.z;
    const int k0 = blockIdx.y * 32;
    const int n0 = blockIdx.x * 32;
    const int tx = threadIdx.x;       // 0..31
    const int ty = threadIdx.y;       // 0..7

    #pragma unroll
    for (int i = 0; i < 4; i++)
        tile[ty + i * 8][tx] = W[(size_t)l * HH * HH + (size_t)(k0 + ty + i * 8) * HH + n0 + tx];
    __syncthreads();

    #pragma unroll
    for (int i = 0; i < 4; i++) {
        const int n = n0 + ty + i * 8;
        const int k = k0 + tx;
        g_Wh[(size_t)l * HH * HH + (size_t)n * HH + k] = __float2half_rn(tile[tx][ty + i * 8]);
    }
}

// ---------------- kernel 3: sparse aggregation -> fp16 plane ----------------
__global__ void __launch_bounds__(128) agg_kernel(const float4* __restrict__ xin) {
    __shared__ uint32_t rowbits[ADJ_WORDS];
    const int b = blockIdx.y;
    const int n = blockIdx.x;
    const int t = threadIdx.x;

    const uint32_t* row = &g_adj[((size_t)b * NN + n) * ADJ_WORDS];
    if (t < ADJ_WORDS) rowbits[t] = row[t];
    __syncthreads();

    const float4* xb = xin + (size_t)b * NN * (HH/4);
    float4 acc = make_float4(0.f, 0.f, 0.f, 0.f);

    #pragma unroll 4
    for (int w = 0; w < ADJ_WORDS; w++) {
        uint32_t bits = rowbits[w];
        while (bits) {
            const int bit = __ffs(bits) - 1;
            bits &= bits - 1;
            const int m = (w << 5) + bit;
            const float4 v = __ldg(&xb[(size_t)m * (HH/4) + t]);
            acc.x += v.x; acc.y += v.y; acc.z += v.z; acc.w += v.w;
        }
    }

    __half2 h01 = __halves2half2(__float2half_rn(acc.x), __float2half_rn(acc.y));
    __half2 h23 = __halves2half2(__float2half_rn(acc.z), __float2half_rn(acc.w));
    const size_t base = ((size_t)b * NN + n) * (HH/2) + 2 * t;  // half2 units
    ((__half2*)g_Ah)[base]     = h01;
    ((__half2*)g_Ah)[base + 1] = h23;
}

// ---------------- kernel 4: cp.async-pipelined single-pass fp16 GEMM + LN ----
// CTA: 64 rows x 512 cols, 512 threads = 16 warps (2 M x 8 N), warp tile 32x64.
// Two cp.async stages; smem rows padded to 40 halves (80 B).
// Per-stage: A 0 (5120 B), W 5120 (40960 B). Stage = 46080 B.
#define STG      46080
#define SG_BIAS  92160                 // 512 f
#define SG_GAMMA 94208
#define SG_BETA  96256
#define SG_PSUM  98304                 // 64 x 8 f
#define SG_PSQ   100352
#define SG_MU    102400                // 64 f
#define SG_RS    102656
#define SM_TOTAL2 102912

__global__ void __launch_bounds__(512, 1) gemm_mma_kernel(
    const __half* __restrict__ Ah,
    const __half* __restrict__ Wh,
    const float* __restrict__ bl, const float* __restrict__ gl, const float* __restrict__ btl,
    const float* __restrict__ resid, float* __restrict__ out)
{
    extern __shared__ char smem[];
    const uint32_t sbase = smem_u32(smem);
    const int tid  = threadIdx.x;
    const int lane = tid & 31;
    const int wid  = tid >> 5;
    const int mwarp = wid >> 3;        // 0..1
    const int nwarp = wid & 7;         // 0..7
    const int row0 = blockIdx.x * 64;

    ((float*)(smem + SG_BIAS))[tid]  = __ldg(&bl[tid]);
    ((float*)(smem + SG_GAMMA))[tid] = __ldg(&gl[tid]);
    ((float*)(smem + SG_BETA))[tid]  = __ldg(&btl[tid]);

    float c[16][4];
    #pragma unroll
    for (int f = 0; f < 16; f++)
        #pragma unroll
        for (int q = 0; q < 4; q++) c[f][q] = 0.f;

    #define LOAD_CHUNK(chk, stg) do {                                              \
        const int kc0_ = (chk) * 32;                                               \
        const uint32_t sb_ = sbase + (stg) * STG;                                  \
        if (tid < 256) {                                                           \
            const int r_ = tid >> 2, seg_ = tid & 3;                               \
            const __half* src = Ah + (size_t)(row0 + r_) * HH + kc0_ + seg_ * 8;   \
            cpa16(sb_ + r_ * 80 + seg_ * 16, src);                                 \
        }                                                                          \
        _Pragma("unroll")                                                          \
        for (int i_ = 0; i_ < 4; i_++) {                                           \
            const int idx_ = tid + i_ * 512;                                       \
            const int r_ = idx_ >> 2, seg_ = idx_ & 3;                             \
            const __half* src = Wh + (size_t)r_ * HH + kc0_ + seg_ * 8;            \
            cpa16(sb_ + 5120 + r_ * 80 + seg_ * 16, src);                          \
        }                                                                          \
        asm volatile("cp.async.commit_group;");                                    \
    } while (0)

    LOAD_CHUNK(0, 0);

    for (int chk = 0; chk < 16; chk++) {
        if (chk + 1 < 16) {
            LOAD_CHUNK(chk + 1, (chk + 1) & 1);
            asm volatile("cp.async.wait_group 1;");
        } else {
            asm volatile("cp.async.wait_group 0;");
        }
        __syncthreads();

        const uint32_t sb = sbase + (chk & 1) * STG;
        #pragma unroll
        for (int ks = 0; ks < 2; ks++) {
            const int amat = lane >> 3;
            const int arow = (amat & 1) * 8 + (lane & 7);
            const int akb  = (ks * 16 + (amat >> 1) * 8) * 2;
            uint32_t ah[2][4], bb[8][2];
            #pragma unroll
            for (int mi = 0; mi < 2; mi++) {
                const uint32_t ra = mwarp * 32 + mi * 16 + arow;
                ldm_x4(ah[mi], sb + ra * 80 + akb);
            }
            const int bmat = lane >> 3;
            const int bn   = (bmat >> 1) * 8 + (lane & 7);
            const int bkb  = (ks * 16 + (bmat & 1) * 8) * 2;
            #pragma unroll
            for (int g = 0; g < 4; g++) {
                uint32_t r[4];
                ldm_x4(r, sb + 5120 + (uint32_t)(nwarp * 64 + g * 16 + bn) * 80 + bkb);
                bb[g*2][0] = r[0]; bb[g*2][1] = r[1];
                bb[g*2+1][0] = r[2]; bb[g*2+1][1] = r[3];
            }
            #pragma unroll
            for (int mi = 0; mi < 2; mi++)
                #pragma unroll
                for (int ni = 0; ni < 8; ni++) mma_fp16(c[mi*8+ni], ah[mi], bb[ni]);
        }
        __syncthreads();
    }

    // ---------------- epilogue: bias + LN + ReLU + residual ----------------
    float* bias_s  = (float*)(smem + SG_BIAS);
    float* gamma_s = (float*)(smem + SG_GAMMA);
    float* beta_s  = (float*)(smem + SG_BETA);
    float* psum_s  = (float*)(smem + SG_PSUM);
    float* psq_s   = (float*)(smem + SG_PSQ);
    float* mu_s    = (float*)(smem + SG_MU);
    float* rs_s    = (float*)(smem + SG_RS);

    float ps[2][2] = {{0.f,0.f},{0.f,0.f}};
    float pq[2][2] = {{0.f,0.f},{0.f,0.f}};
    #pragma unroll
    for (int mi = 0; mi < 2; mi++)
        #pragma unroll
        for (int ni = 0; ni < 8; ni++) {
            const int f = mi*8 + ni;
            #pragma unroll
            for (int h = 0; h < 2; h++)
                #pragma unroll
                for (int j = 0; j < 2; j++) {
                    const int col = nwarp*64 + ni*8 + (lane & 3)*2 + j;
                    const float v = c[f][h*2+j] + bias_s[col];
                    c[f][h*2+j] = v;
                    ps[mi][h] += v;
                    pq[mi][h] += v * v;
                }
        }
    #pragma unroll
    for (int mi = 0; mi < 2; mi++)
        #pragma unroll
        for (int h = 0; h < 2; h++) {
            #pragma unroll
            for (int off = 1; off < 4; off <<= 1) {
                ps[mi][h] += __shfl_xor_sync(0xffffffffu, ps[mi][h], off);
                pq[mi][h] += __shfl_xor_sync(0xffffffffu, pq[mi][h], off);
            }
        }
    if ((lane & 3) == 0) {
        #pragma unroll
        for (int mi = 0; mi < 2; mi++)
            #pragma unroll
            for (int h = 0; h < 2; h++) {
                const int rl = mwarp*32 + mi*16 + h*8 + (lane >> 2);
                psum_s[rl*8 + nwarp] = ps[mi][h];
                psq_s [rl*8 + nwarp] = pq[mi][h];
            }
    }
    __syncthreads();
    if (tid < 64) {
        float s = 0.f, q = 0.f;
        #pragma unroll
        for (int w = 0; w < 8; w++) { s += psum_s[tid*8 + w]; q += psq_s[tid*8 + w]; }
        const float mu = s * (1.0f / HH);
        const float var = q * (1.0f / HH) - mu * mu;
        mu_s[tid] = mu;
        rs_s[tid] = rsqrtf(var + LN_EPS);
    }
    __syncthreads();

    #pragma unroll
    for (int mi = 0; mi < 2; mi++)
        #pragma unroll
        for (int h = 0; h < 2; h++) {
            const int rl = mwarp*32 + mi*16 + h*8 + (lane >> 2);
            const int grow = row0 + rl;
            const float mu = mu_s[rl];
            const float rs = rs_s[rl];
            #pragma unroll
            for (int ni = 0; ni < 8; ni++) {
                const int f = mi*8 + ni;
                const int col = nwarp*64 + ni*8 + (lane & 3)*2;
                float2 o;
                o.x = fmaxf((c[f][h*2+0] - mu) * rs * gamma_s[col]   + beta_s[col],   0.f);
                o.y = fmaxf((c[f][h*2+1] - mu) * rs * gamma_s[col+1] + beta_s[col+1], 0.f);
                if (resid != nullptr) {
                    const float2 rv = __ldg((const float2*)&resid[(size_t)grow * HH + col]);
                    o.x += rv.x; o.y += rv.y;
                }
                *(float2*)&out[(size_t)grow * HH + col] = o;
            }
        }
}

// ---------------- launcher ----------------
extern "C" void kernel_launch(void* const* d_in, const int* in_sizes, int n_in,
                              void* d_out, int out_size) {
    (void)in_sizes; (void)n_in; (void)out_size;
    const float*  node_features = (const float*)d_in[0];   // [8,2048,512]
    const float2* coords        = (const float2*)d_in[1];  // [8,2048,2]
    const float*  W             = (const float*)d_in[2];   // [3,512,512]
    const float*  bvec          = (const float*)d_in[3];   // [3,512]
    const float*  gamma         = (const float*)d_in[4];   // [3,512]
    const float*  beta          = (const float*)d_in[5];   // [3,512]
    float*        outp          = (float*)d_out;           // [8,2048,512]

    float4* gx;  cudaGetSymbolAddress((void**)&gx,  g_x4);
    __half *ah, *wh;
    cudaGetSymbolAddress((void**)&ah, g_Ah);
    cudaGetSymbolAddress((void**)&wh, g_Wh);

    cudaFuncSetAttribute(gemm_mma_kernel, cudaFuncAttributeMaxDynamicSharedMemorySize, SM_TOTAL2);

    zero_adj_kernel<<<(BB * NN * ADJ_WORDS + 255) / 256, 256>>>();
    topk_adj_kernel<<<dim3(NN / 8, BB), 256>>>(coords);
    convw_kernel<<<dim3(16, 16, 3), dim3(32, 8)>>>(W);

    for (int l = 0; l < NLAYERS; l++) {
        const float4* xin = (l == 0) ? (const float4*)node_features : (const float4*)gx;
        agg_kernel<<<dim3(NN, BB), 128>>>(xin);

        const float* resid = (l == 0) ? nullptr : (const float*)gx;
        float* out = (l == NLAYERS - 1) ? outp : (float*)gx;
        gemm_mma_kernel<<<MTOT / 64, 512, SM_TOTAL2>>>(
            ah, wh + (size_t)l * HH * HH,
            bvec + (size_t)l * HH, gamma + (size_t)l * HH, beta + (size_t)l * HH,
            resid, out);
    }
}

// round 10
// speedup vs baseline: 2.6043x; 1.1270x over previous
#include <cuda_runtime.h>
#include <cuda_bf16.h>
#include <cuda_fp16.h>
#include <stdint.h>

// Problem constants
#define BB 8
#define NN 2048
#define HH 512
#define NSEL 9
#define NLAYERS 3
#define LN_EPS 1e-5f

#define ADJ_WORDS 64
#define MTOT (BB*NN)        // 16384 rows

// ---------------- device scratch ----------------
__device__ uint32_t g_adj[BB * NN * ADJ_WORDS];     // 4 MB
__device__ float4   g_x4[BB * NN * (HH/4)];         // 32 MB current x (fp32)
__device__ __half   g_Ah[MTOT * HH];                // 16 MB agg fp16
__device__ __half   g_Wh[NLAYERS * HH * HH];        // W^T fp16  [l][n][k]

// ---------------- helpers (sm_80+ only) ----------------
__device__ __forceinline__ uint32_t smem_u32(const void* p) {
    uint32_t a;
    asm("{ .reg .u64 t; cvta.to.shared.u64 t, %1; cvt.u32.u64 %0, t; }" : "=r"(a) : "l"(p));
    return a;
}
__device__ __forceinline__ void ldm_x4(uint32_t* r, uint32_t addr) {
    asm volatile("ldmatrix.sync.aligned.m8n8.x4.shared.b16 {%0,%1,%2,%3}, [%4];"
                 : "=r"(r[0]), "=r"(r[1]), "=r"(r[2]), "=r"(r[3]) : "r"(addr));
}
__device__ __forceinline__ void mma_fp16(float* c, const uint32_t* a, const uint32_t* b) {
    asm volatile("mma.sync.aligned.m16n8k16.row.col.f32.f16.f16.f32 "
                 "{%0,%1,%2,%3}, {%4,%5,%6,%7}, {%8,%9}, {%0,%1,%2,%3};"
                 : "+f"(c[0]), "+f"(c[1]), "+f"(c[2]), "+f"(c[3])
                 : "r"(a[0]), "r"(a[1]), "r"(a[2]), "r"(a[3]), "r"(b[0]), "r"(b[1]));
}
__device__ __forceinline__ void cpa16(uint32_t s, const void* g) {
    asm volatile("cp.async.cg.shared.global [%0], [%1], 16;" :: "r"(s), "l"(g));
}

// ---------------- kernel 0: merged setup (zero adjacency + W transpose/fp16) ----
// blocks [0,128): zero g_adj; blocks [128,896): convw (flattened 3*16*16 grid).
__global__ void __launch_bounds__(256) setup_kernel(const float* __restrict__ W) {
    __shared__ float tile[32][33];
    if (blockIdx.x < 128) {
        for (int j = blockIdx.x * 256 + threadIdx.x; j < BB * NN * ADJ_WORDS; j += 128 * 256)
            g_adj[j] = 0u;
        return;
    }
    const int bid = blockIdx.x - 128;
    const int l   = bid >> 8;            // 0..2
    const int rem = bid & 255;
    const int n0  = (rem & 15) * 32;
    const int k0  = (rem >> 4) * 32;
    const int tx  = threadIdx.x & 31;
    const int ty  = threadIdx.x >> 5;    // 0..7

    #pragma unroll
    for (int i = 0; i < 4; i++)
        tile[ty + i * 8][tx] = W[(size_t)l * HH * HH + (size_t)(k0 + ty + i * 8) * HH + n0 + tx];
    __syncthreads();

    #pragma unroll
    for (int i = 0; i < 4; i++) {
        const int n = n0 + ty + i * 8;
        const int k = k0 + tx;
        g_Wh[(size_t)l * HH * HH + (size_t)n * HH + k] = __float2half_rn(tile[tx][ty + i * 8]);
    }
}

// ---------------- kernel 1: warp-per-row top-k + adjacency build ----------------
__global__ void __launch_bounds__(256) topk_adj_kernel(const float2* __restrict__ coords) {
    __shared__ float2 sc[NN];
    const int b    = blockIdx.y;
    const int tid  = threadIdx.x;
    const int lane = tid & 31;
    const int wrp  = tid >> 5;                 // 0..7
    const int n    = blockIdx.x * 8 + wrp;

    const float2* cb = coords + (size_t)b * NN;
    for (int i = tid; i < NN; i += 256) sc[i] = cb[i];
    __syncthreads();

    const float xn = sc[n].x, yn = sc[n].y;
    const float sqn = __fadd_rn(__fmul_rn(xn, xn), __fmul_rn(yn, yn));

    unsigned long long top[NSEL];
    #pragma unroll
    for (int j = 0; j < NSEL; j++) top[j] = ~0ull;

    for (int m = lane; m < NN; m += 32) {
        const float xm = sc[m].x, ym = sc[m].y;
        const float sqm = __fadd_rn(__fmul_rn(xm, xm), __fmul_rn(ym, ym));
        const float dot = __fmaf_rn(yn, ym, __fmul_rn(xn, xm));
        const float d2  = __fsub_rn(__fadd_rn(sqn, sqm), __fmul_rn(2.0f, dot));
        uint32_t fb = __float_as_uint(d2);
        fb = (fb & 0x80000000u) ? ~fb : (fb | 0x80000000u);
        const unsigned long long k = ((unsigned long long)fb << 32) | (uint32_t)m;
        if (k < top[NSEL - 1]) {
            top[NSEL - 1] = k;
            #pragma unroll
            for (int j = NSEL - 1; j > 0; j--) {
                if (top[j] < top[j - 1]) {
                    unsigned long long t = top[j]; top[j] = top[j - 1]; top[j - 1] = t;
                }
            }
        }
    }

    int p = 0;
    for (int r = 0; r < NSEL; r++) {
        unsigned long long cand = (p < NSEL) ? top[p] : ~0ull;
        unsigned long long mn = cand;
        #pragma unroll
        for (int off = 16; off > 0; off >>= 1) {
            unsigned long long o = __shfl_xor_sync(0xffffffffu, mn, off);
            mn = (o < mn) ? o : mn;
        }
        if (cand == mn) p++;
        if (r > 0 && lane == 0) {
            const int m = (int)(mn & 0xffffffffu);
            atomicOr(&g_adj[((size_t)b * NN + n) * ADJ_WORDS + (m >> 5)], 1u << (m & 31));
            atomicOr(&g_adj[((size_t)b * NN + m) * ADJ_WORDS + (n >> 5)], 1u << (n & 31));
        }
    }
}

// ---------------- kernel 3: sparse aggregation via smem neighbor list ----------
// Decode bitmask ONCE (deterministic ascending order), then pure coalesced loads.
__global__ void __launch_bounds__(128) agg_kernel(const float4* __restrict__ xin) {
    __shared__ uint32_t rowbits[ADJ_WORDS];
    __shared__ int s_off[ADJ_WORDS];
    __shared__ int s_nbr[512];
    __shared__ int s_cnt;
    const int b = blockIdx.y;
    const int n = blockIdx.x;
    const int t = threadIdx.x;

    const uint32_t* row = &g_adj[((size_t)b * NN + n) * ADJ_WORDS];
    if (t < ADJ_WORDS) rowbits[t] = row[t];
    __syncthreads();

    if (t == 0) {
        int off = 0;
        #pragma unroll
        for (int w = 0; w < ADJ_WORDS; w++) { s_off[w] = off; off += __popc(rowbits[w]); }
        s_cnt = off;
    }
    __syncthreads();
    if (t < ADJ_WORDS) {
        uint32_t bits = rowbits[t];
        int pos = s_off[t];
        while (bits) {
            const int bit = __ffs(bits) - 1;
            bits &= bits - 1;
            s_nbr[pos++] = (t << 5) + bit;
        }
    }
    __syncthreads();

    const int deg = s_cnt;
    const float4* xb = xin + (size_t)b * NN * (HH/4);
    float4 acc = make_float4(0.f, 0.f, 0.f, 0.f);
    for (int i = 0; i < deg; i++) {
        const float4 v = __ldg(&xb[(size_t)s_nbr[i] * (HH/4) + t]);
        acc.x += v.x; acc.y += v.y; acc.z += v.z; acc.w += v.w;
    }

    __half2 h01 = __halves2half2(__float2half_rn(acc.x), __float2half_rn(acc.y));
    __half2 h23 = __halves2half2(__float2half_rn(acc.z), __float2half_rn(acc.w));
    const size_t base = ((size_t)b * NN + n) * (HH/2) + 2 * t;
    ((__half2*)g_Ah)[base]     = h01;
    ((__half2*)g_Ah)[base + 1] = h23;
}

// ---------------- kernel 4: cp.async-pipelined fp16 GEMM + LN, K-chunk 64 ----
// CTA: 64 rows x 512 cols, 512 threads = 16 warps (2 M x 8 N), warp tile 32x64.
// Two cp.async stages; smem rows padded to 72 halves (144 B) -> ldmatrix conflict-free.
// Per-stage: A 0 (9216 B), W 9216 (73728 B). Stage = 82944 B.
#define STG      82944
#define SG_BIAS  165888                // 512 f
#define SG_GAMMA 167936
#define SG_BETA  169984
#define SG_PSUM  172032                // 64 x 8 f
#define SG_PSQ   174080
#define SG_MU    176128                // 64 f
#define SG_RS    176384
#define SM_TOTAL2 176640

__global__ void __launch_bounds__(512, 1) gemm_mma_kernel(
    const __half* __restrict__ Ah,
    const __half* __restrict__ Wh,
    const float* __restrict__ bl, const float* __restrict__ gl, const float* __restrict__ btl,
    const float* __restrict__ resid, float* __restrict__ out)
{
    extern __shared__ char smem[];
    const uint32_t sbase = smem_u32(smem);
    const int tid  = threadIdx.x;
    const int lane = tid & 31;
    const int wid  = tid >> 5;
    const int mwarp = wid >> 3;        // 0..1
    const int nwarp = wid & 7;         // 0..7
    const int row0 = blockIdx.x * 64;

    ((float*)(smem + SG_BIAS))[tid]  = __ldg(&bl[tid]);
    ((float*)(smem + SG_GAMMA))[tid] = __ldg(&gl[tid]);
    ((float*)(smem + SG_BETA))[tid]  = __ldg(&btl[tid]);

    float c[16][4];
    #pragma unroll
    for (int f = 0; f < 16; f++)
        #pragma unroll
        for (int q = 0; q < 4; q++) c[f][q] = 0.f;

    #define LOAD_CHUNK(chk, stg) do {                                              \
        const int kc0_ = (chk) * 64;                                               \
        const uint32_t sb_ = sbase + (stg) * STG;                                  \
        {                                                                          \
            const int r_ = tid >> 3, seg_ = tid & 7;                               \
            cpa16(sb_ + r_ * 144 + seg_ * 16,                                      \
                  Ah + (size_t)(row0 + r_) * HH + kc0_ + seg_ * 8);                \
        }                                                                          \
        _Pragma("unroll")                                                          \
        for (int i_ = 0; i_ < 8; i_++) {                                           \
            const int idx_ = tid + i_ * 512;                                       \
            const int r_ = idx_ >> 3, seg_ = idx_ & 7;                             \
            cpa16(sb_ + 9216 + r_ * 144 + seg_ * 16,                               \
                  Wh + (size_t)r_ * HH + kc0_ + seg_ * 8);                         \
        }                                                                          \
        asm volatile("cp.async.commit_group;");                                    \
    } while (0)

    LOAD_CHUNK(0, 0);

    for (int chk = 0; chk < 8; chk++) {
        if (chk + 1 < 8) {
            LOAD_CHUNK(chk + 1, (chk + 1) & 1);
            asm volatile("cp.async.wait_group 1;");
        } else {
            asm volatile("cp.async.wait_group 0;");
        }
        __syncthreads();

        const uint32_t sb = sbase + (chk & 1) * STG;
        #pragma unroll
        for (int ks = 0; ks < 4; ks++) {
            const int amat = lane >> 3;
            const int arow = (amat & 1) * 8 + (lane & 7);
            const int akb  = (ks * 16 + (amat >> 1) * 8) * 2;
            uint32_t ah[2][4], bb[8][2];
            #pragma unroll
            for (int mi = 0; mi < 2; mi++) {
                const uint32_t ra = mwarp * 32 + mi * 16 + arow;
                ldm_x4(ah[mi], sb + ra * 144 + akb);
            }
            const int bmat = lane >> 3;
            const int bn   = (bmat >> 1) * 8 + (lane & 7);
            const int bkb  = (ks * 16 + (bmat & 1) * 8) * 2;
            #pragma unroll
            for (int g = 0; g < 4; g++) {
                uint32_t r[4];
                ldm_x4(r, sb + 9216 + (uint32_t)(nwarp * 64 + g * 16 + bn) * 144 + bkb);
                bb[g*2][0] = r[0]; bb[g*2][1] = r[1];
                bb[g*2+1][0] = r[2]; bb[g*2+1][1] = r[3];
            }
            #pragma unroll
            for (int mi = 0; mi < 2; mi++)
                #pragma unroll
                for (int ni = 0; ni < 8; ni++) mma_fp16(c[mi*8+ni], ah[mi], bb[ni]);
        }
        __syncthreads();
    }

    // ---------------- epilogue: bias + LN + ReLU + residual ----------------
    float* bias_s  = (float*)(smem + SG_BIAS);
    float* gamma_s = (float*)(smem + SG_GAMMA);
    float* beta_s  = (float*)(smem + SG_BETA);
    float* psum_s  = (float*)(smem + SG_PSUM);
    float* psq_s   = (float*)(smem + SG_PSQ);
    float* mu_s    = (float*)(smem + SG_MU);
    float* rs_s    = (float*)(smem + SG_RS);

    float ps[2][2] = {{0.f,0.f},{0.f,0.f}};
    float pq[2][2] = {{0.f,0.f},{0.f,0.f}};
    #pragma unroll
    for (int mi = 0; mi < 2; mi++)
        #pragma unroll
        for (int ni = 0; ni < 8; ni++) {
            const int f = mi*8 + ni;
            #pragma unroll
            for (int h = 0; h < 2; h++)
                #pragma unroll
                for (int j = 0; j < 2; j++) {
                    const int col = nwarp*64 + ni*8 + (lane & 3)*2 + j;
                    const float v = c[f][h*2+j] + bias_s[col];
                    c[f][h*2+j] = v;
                    ps[mi][h] += v;
                    pq[mi][h] += v * v;
                }
        }
    #pragma unroll
    for (int mi = 0; mi < 2; mi++)
        #pragma unroll
        for (int h = 0; h < 2; h++) {
            #pragma unroll
            for (int off = 1; off < 4; off <<= 1) {
                ps[mi][h] += __shfl_xor_sync(0xffffffffu, ps[mi][h], off);
                pq[mi][h] += __shfl_xor_sync(0xffffffffu, pq[mi][h], off);
            }
        }
    if ((lane & 3) == 0) {
        #pragma unroll
        for (int mi = 0; mi < 2; mi++)
            #pragma unroll
            for (int h = 0; h < 2; h++) {
                const int rl = mwarp*32 + mi*16 + h*8 + (lane >> 2);
                psum_s[rl*8 + nwarp] = ps[mi][h];
                psq_s [rl*8 + nwarp] = pq[mi][h];
            }
    }
    __syncthreads();
    if (tid < 64) {
        float s = 0.f, q = 0.f;
        #pragma unroll
        for (int w = 0; w < 8; w++) { s += psum_s[tid*8 + w]; q += psq_s[tid*8 + w]; }
        const float mu = s * (1.0f / HH);
        const float var = q * (1.0f / HH) - mu * mu;
        mu_s[tid] = mu;
        rs_s[tid] = rsqrtf(var + LN_EPS);
    }
    __syncthreads();

    #pragma unroll
    for (int mi = 0; mi < 2; mi++)
        #pragma unroll
        for (int h = 0; h < 2; h++) {
            const int rl = mwarp*32 + mi*16 + h*8 + (lane >> 2);
            const int grow = row0 + rl;
            const float mu = mu_s[rl];
            const float rs = rs_s[rl];
            #pragma unroll
            for (int ni = 0; ni < 8; ni++) {
                const int f = mi*8 + ni;
                const int col = nwarp*64 + ni*8 + (lane & 3)*2;
                float2 o;
                o.x = fmaxf((c[f][h*2+0] - mu) * rs * gamma_s[col]   + beta_s[col],   0.f);
                o.y = fmaxf((c[f][h*2+1] - mu) * rs * gamma_s[col+1] + beta_s[col+1], 0.f);
                if (resid != nullptr) {
                    const float2 rv = __ldg((const float2*)&resid[(size_t)grow * HH + col]);
                    o.x += rv.x; o.y += rv.y;
                }
                *(float2*)&out[(size_t)grow * HH + col] = o;
            }
        }
}

// ---------------- launcher ----------------
extern "C" void kernel_launch(void* const* d_in, const int* in_sizes, int n_in,
                              void* d_out, int out_size) {
    (void)in_sizes; (void)n_in; (void)out_size;
    const float*  node_features = (const float*)d_in[0];   // [8,2048,512]
    const float2* coords        = (const float2*)d_in[1];  // [8,2048,2]
    const float*  W             = (const float*)d_in[2];   // [3,512,512]
    const float*  bvec          = (const float*)d_in[3];   // [3,512]
    const float*  gamma         = (const float*)d_in[4];   // [3,512]
    const float*  beta          = (const float*)d_in[5];   // [3,512]
    float*        outp          = (float*)d_out;           // [8,2048,512]

    float4* gx;  cudaGetSymbolAddress((void**)&gx,  g_x4);
    __half *ah, *wh;
    cudaGetSymbolAddress((void**)&ah, g_Ah);
    cudaGetSymbolAddress((void**)&wh, g_Wh);

    cudaFuncSetAttribute(gemm_mma_kernel, cudaFuncAttributeMaxDynamicSharedMemorySize, SM_TOTAL2);

    // launch 0: setup (zero adj + convw)   -> gemm lands at profiled index 3
    setup_kernel<<<896, 256>>>(W);
    topk_adj_kernel<<<dim3(NN / 8, BB), 256>>>(coords);

    for (int l = 0; l < NLAYERS; l++) {
        const float4* xin = (l == 0) ? (const float4*)node_features : (const float4*)gx;
        agg_kernel<<<dim3(NN, BB), 128>>>(xin);

        const float* resid = (l == 0) ? nullptr : (const float*)gx;
        float* out = (l == NLAYERS - 1) ? outp : (float*)gx;
        gemm_mma_kernel<<<MTOT / 64, 512, SM_TOTAL2>>>(
            ah, wh + (size_t)l * HH * HH,
            bvec + (size_t)l * HH, gamma + (size_t)l * HH, beta + (size_t)l * HH,
            resid, out);
    }
}